// round 8
// baseline (speedup 1.0000x reference)
#include <cuda_runtime.h>
#include <cuda_bf16.h>
#include <cstdint>

// ---------------------------------------------------------------------------
// Problem constants
// ---------------------------------------------------------------------------
#define S_ 2048
#define DIM_ 2048
#define H_ 16
#define NOPE_ 128
#define ROPE_ 64
#define VD_ 128
#define LORA_ 512
#define QKH_ 192            // NOPE + ROPE
#define KVW_ 576            // LORA + ROPE
#define NQKV_ 3712          // 3072 (q) + 640 (kv padded)
#define SCALE_ 0.07216878364870323f  // 192^-0.5

// ---------------------------------------------------------------------------
// Scratch
// ---------------------------------------------------------------------------
__device__ float d_qc    [(long)S_ * NQKV_];         // [q | kvpad] fp32

__device__ __nv_bfloat16 d_xhi[(long)S_ * DIM_],      d_xlo[(long)S_ * DIM_];
__device__ __nv_bfloat16 d_wqkvhi[(long)NQKV_ * DIM_],d_wqkvlo[(long)NQKV_ * DIM_];
__device__ __nv_bfloat16 d_wohi[(long)DIM_ * DIM_],   d_wolo[(long)DIM_ * DIM_];
__device__ __nv_bfloat16 d_wkvbhi[(long)H_ * 256 * LORA_], d_wkvblo[(long)H_ * 256 * LORA_];
__device__ __nv_bfloat16 d_wukThi[(long)H_ * LORA_ * NOPE_], d_wukTlo[(long)H_ * LORA_ * NOPE_];
__device__ __nv_bfloat16 d_qchi[(long)S_ * NQKV_],    d_qclo[(long)S_ * NQKV_];
__device__ __nv_bfloat16 d_qeffhi[(long)H_ * S_ * KVW_], d_qefflo[(long)H_ * S_ * KVW_];
__device__ __nv_bfloat16 d_keffhi[(long)S_ * KVW_],   d_kefflo[(long)S_ * KVW_];
__device__ __nv_bfloat16 d_keffThi[(long)LORA_ * S_], d_keffTlo[(long)LORA_ * S_];
// scores (pre-softmax, bf16 hi/lo) and attn (post-softmax) share these, in place
__device__ __nv_bfloat16 d_attnhi[(long)H_ * S_ * S_],d_attnlo[(long)H_ * S_ * S_];
__device__ __nv_bfloat16 d_o1hi[(long)H_ * S_ * LORA_], d_o1lo[(long)H_ * S_ * LORA_];
__device__ __nv_bfloat16 d_o2hi[(long)S_ * DIM_],     d_o2lo[(long)S_ * DIM_];

// ---------------------------------------------------------------------------
// Helpers
// ---------------------------------------------------------------------------
__device__ __forceinline__ uint32_t smem_u32(const void* p) {
    uint32_t a;
    asm("{ .reg .u64 t; cvta.to.shared.u64 t, %1; cvt.u32.u64 %0, t; }"
        : "=r"(a) : "l"(p));
    return a;
}

__device__ __forceinline__ void ldsm_x4(uint32_t* r, uint32_t addr) {
    asm volatile("ldmatrix.sync.aligned.m8n8.x4.shared.b16 {%0,%1,%2,%3}, [%4];"
                 : "=r"(r[0]), "=r"(r[1]), "=r"(r[2]), "=r"(r[3]) : "r"(addr));
}
__device__ __forceinline__ void ldsm_x2(uint32_t* r, uint32_t addr) {
    asm volatile("ldmatrix.sync.aligned.m8n8.x2.shared.b16 {%0,%1}, [%2];"
                 : "=r"(r[0]), "=r"(r[1]) : "r"(addr));
}
__device__ __forceinline__ void mma16816(float* c, const uint32_t* a, const uint32_t* b) {
    asm volatile(
        "mma.sync.aligned.m16n8k16.row.col.f32.bf16.bf16.f32 "
        "{%0,%1,%2,%3}, {%4,%5,%6,%7}, {%8,%9}, {%0,%1,%2,%3};"
        : "+f"(c[0]), "+f"(c[1]), "+f"(c[2]), "+f"(c[3])
        : "r"(a[0]), "r"(a[1]), "r"(a[2]), "r"(a[3]), "r"(b[0]), "r"(b[1]));
}

__device__ __forceinline__ void split2(float v, __nv_bfloat16& h, __nv_bfloat16& l) {
    h = __float2bfloat16(v);
    l = __float2bfloat16(v - __bfloat162float(h));
}

// ---------------------------------------------------------------------------
// bf16 split-precision GEMM via mma.sync:
//   C(z) = alpha * A(z)(M,K) @ B(z)(N,K)^T
//   C ~= Ahi.Bhi + Ahi.Blo + Alo.Bhi  (fp32 accum)
// CTA tile 128x128, K chunk 32, cp.async double buffer, 2 CTAs/SM,
// ONE __syncthreads per chunk.
// SMEM: 128 rows x 80B pitch -> conflict-free ldmatrix.
// grid = (N/128, M/128, Z); 256 threads (8 warps, warp 64x32).
// causal: 1 = skip tiles with bx > by; 2 = Klim = min(K, row0+128)
// ---------------------------------------------------------------------------
#define TILE_B 10240            // 128 * 80
#define STAGE_B 40960           // 4 tiles
#define DSMEM_BYTES 81920       // 2 stages

__device__ __forceinline__ void load_tile32(uint32_t dst,
                                            const __nv_bfloat16* __restrict__ src,
                                            int rbase, int ld, int k0, int tid)
{
#pragma unroll
    for (int t = 0; t < 2; t++) {
        int o = tid + t * 256;          // 0..511 : 128 rows x 4 x 16B
        int row = o >> 2, c = o & 3;
        const void* g = (const void*)(src + (long)(rbase + row) * ld + k0 + c * 8);
        asm volatile("cp.async.cg.shared.global [%0], [%1], 16;"
                     :: "r"(dst + row * 80 + c * 16), "l"(g));
    }
}

__global__ void __launch_bounds__(256, 2)
tgemm(const __nv_bfloat16* __restrict__ Ahi, const __nv_bfloat16* __restrict__ Alo,
      long sA, int lda,
      const __nv_bfloat16* __restrict__ Bhi, const __nv_bfloat16* __restrict__ Blo,
      long sB, int ldb,
      float* Cf, __nv_bfloat16* Chi, __nv_bfloat16* Clo,
      long sC, int ldc,
      int K, float alpha, int causal)
{
    const int bx = blockIdx.x, by = blockIdx.y, z = blockIdx.z;
    if (causal == 1 && bx > by) return;
    const int row0 = by * 128, col0 = bx * 128;
    int Klim = (causal == 2) ? min(K, row0 + 128) : K;
    const int nc = Klim >> 5;

    Ahi += (long)z * sA;  Alo += (long)z * sA;
    Bhi += (long)z * sB;  Blo += (long)z * sB;
    if (Cf)  Cf  += (long)z * sC;
    if (Chi) { Chi += (long)z * sC; Clo += (long)z * sC; }

    extern __shared__ char dsm[];
    const uint32_t s0 = smem_u32(dsm);

    const int tid = threadIdx.x;
    const int lane = tid & 31;
    const int wid = tid >> 5;
    const int wm = wid & 1;          // 0..1  (M)
    const int wn = wid >> 1;         // 0..3  (N)

    float acc[4][4][4];
#pragma unroll
    for (int mt = 0; mt < 4; mt++)
#pragma unroll
        for (int nt = 0; nt < 4; nt++)
#pragma unroll
            for (int e = 0; e < 4; e++) acc[mt][nt][e] = 0.f;

    // prologue: fill stage 0
    {
        uint32_t sb = s0;
        load_tile32(sb,              Ahi, row0, lda, 0, tid);
        load_tile32(sb + TILE_B,     Alo, row0, lda, 0, tid);
        load_tile32(sb + 2 * TILE_B, Bhi, col0, ldb, 0, tid);
        load_tile32(sb + 3 * TILE_B, Blo, col0, ldb, 0, tid);
        asm volatile("cp.async.commit_group;" ::: "memory");
    }

    const uint32_t a_off = (wm * 64 + (lane & 15)) * 80 + ((lane >> 4) << 4);
    const uint32_t b_off = (wn * 32 + (lane & 7)) * 80 + (((lane >> 3) & 1) << 4);

    for (int i = 0; i < nc; i++) {
        // group(i) is the only outstanding group here -> wait all
        asm volatile("cp.async.wait_group 0;" ::: "memory");
        __syncthreads();   // data visible to all; compute(i-1) readers done (WAR)

        if (i + 1 < nc) {
            uint32_t sb = s0 + ((i + 1) & 1) * STAGE_B;
            int k0 = (i + 1) << 5;
            load_tile32(sb,              Ahi, row0, lda, k0, tid);
            load_tile32(sb + TILE_B,     Alo, row0, lda, k0, tid);
            load_tile32(sb + 2 * TILE_B, Bhi, col0, ldb, k0, tid);
            load_tile32(sb + 3 * TILE_B, Blo, col0, ldb, k0, tid);
            asm volatile("cp.async.commit_group;" ::: "memory");
        }

        const uint32_t sb = s0 + (i & 1) * STAGE_B;
#pragma unroll
        for (int ks = 0; ks < 2; ks++) {
            const uint32_t kb = ks * 32;
            uint32_t bh[4][2], bl[4][2];
#pragma unroll
            for (int nt = 0; nt < 4; nt++) {
                ldsm_x2(bh[nt], sb + 2 * TILE_B + b_off + nt * (8 * 80) + kb);
                ldsm_x2(bl[nt], sb + 3 * TILE_B + b_off + nt * (8 * 80) + kb);
            }
#pragma unroll
            for (int mt = 0; mt < 4; mt++) {
                uint32_t ah[4], al[4];
                ldsm_x4(ah, sb + a_off + mt * (16 * 80) + kb);
                ldsm_x4(al, sb + TILE_B + a_off + mt * (16 * 80) + kb);
#pragma unroll
                for (int nt = 0; nt < 4; nt++) {
                    mma16816(acc[mt][nt], ah, bh[nt]);
                    mma16816(acc[mt][nt], ah, bl[nt]);
                    mma16816(acc[mt][nt], al, bh[nt]);
                }
            }
        }
    }
    __syncthreads();   // all warps done with smem buffers before stage reuse

    // ---------------- epilogue: stage through smem ----------------
    float* stage = (float*)dsm;   // pitch 132 f32: 128*132*4 = 67584 <= 81920
#pragma unroll
    for (int mt = 0; mt < 4; mt++) {
        int r = wm * 64 + mt * 16 + (lane >> 2);
#pragma unroll
        for (int nt = 0; nt < 4; nt++) {
            int c = wn * 32 + nt * 8 + (lane & 3) * 2;
            stage[r * 132 + c]           = acc[mt][nt][0] * alpha;
            stage[r * 132 + c + 1]       = acc[mt][nt][1] * alpha;
            stage[(r + 8) * 132 + c]     = acc[mt][nt][2] * alpha;
            stage[(r + 8) * 132 + c + 1] = acc[mt][nt][3] * alpha;
        }
    }
    __syncthreads();

#pragma unroll
    for (int it = 0; it < 16; it++) {
        int g = tid + it * 256;
        int m = g >> 5, cg = (g & 31) * 4;
        float v0 = stage[m * 132 + cg + 0];
        float v1 = stage[m * 132 + cg + 1];
        float v2 = stage[m * 132 + cg + 2];
        float v3 = stage[m * 132 + cg + 3];
        long off = (long)(row0 + m) * ldc + col0 + cg;
        if (Cf) {
            float4 v = make_float4(v0, v1, v2, v3);
            *(float4*)(Cf + off) = v;
        }
        if (Chi) {
            __nv_bfloat16 h0, h1, h2, h3, l0, l1, l2, l3;
            split2(v0, h0, l0); split2(v1, h1, l1);
            split2(v2, h2, l2); split2(v3, h3, l3);
            *(__nv_bfloat162*)(Chi + off)     = __nv_bfloat162(h0, h1);
            *(__nv_bfloat162*)(Chi + off + 2) = __nv_bfloat162(h2, h3);
            *(__nv_bfloat162*)(Clo + off)     = __nv_bfloat162(l0, l1);
            *(__nv_bfloat162*)(Clo + off + 2) = __nv_bfloat162(l2, l3);
        }
    }
}

// ---------------------------------------------------------------------------
// Pointwise / prep kernels
// ---------------------------------------------------------------------------
__global__ void split_kernel(const float4* __restrict__ in,
                             __nv_bfloat162* __restrict__ hi,
                             __nv_bfloat162* __restrict__ lo, long n4)
{
    long i = (long)blockIdx.x * blockDim.x + threadIdx.x;
    if (i < n4) {
        float4 v = in[i];
        __nv_bfloat16 h0, h1, h2, h3, l0, l1, l2, l3;
        split2(v.x, h0, l0); split2(v.y, h1, l1);
        split2(v.z, h2, l2); split2(v.w, h3, l3);
        hi[2 * i]     = __nv_bfloat162(h0, h1);
        hi[2 * i + 1] = __nv_bfloat162(h2, h3);
        lo[2 * i]     = __nv_bfloat162(l0, l1);
        lo[2 * i + 1] = __nv_bfloat162(l2, l3);
    }
}

// concat wq (3072x2048) + wkv_a (576x2048, zero-padded to 640) -> 3712x2048
__global__ void split_concat_wqkv(const float4* __restrict__ wq,
                                  const float4* __restrict__ wkva,
                                  __nv_bfloat162* __restrict__ hi,
                                  __nv_bfloat162* __restrict__ lo)
{
    long i = (long)blockIdx.x * blockDim.x + threadIdx.x;  // float4 index
    long n4 = (long)NQKV_ * DIM_ / 4;
    if (i < n4) {
        long r = i / (DIM_ / 4);
        float4 v;
        if (r < 3072)            v = wq[i];
        else if (r < 3072 + KVW_) v = wkva[i - (long)3072 * (DIM_ / 4)];
        else                     v = make_float4(0.f, 0.f, 0.f, 0.f);
        __nv_bfloat16 h0, h1, h2, h3, l0, l1, l2, l3;
        split2(v.x, h0, l0); split2(v.y, h1, l1);
        split2(v.z, h2, l2); split2(v.w, h3, l3);
        hi[2 * i]     = __nv_bfloat162(h0, h1);
        hi[2 * i + 1] = __nv_bfloat162(h2, h3);
        lo[2 * i]     = __nv_bfloat162(l0, l1);
        lo[2 * i + 1] = __nv_bfloat162(l2, l3);
    }
}

// w_ukT[h][c][d] = wkv_b[(h*256+d)*512 + c], split. grid(16,4,16), block(32,32)
__global__ void wukt_kernel(const float* __restrict__ wkvb,
                            __nv_bfloat16* __restrict__ hi,
                            __nv_bfloat16* __restrict__ lo)
{
    __shared__ float tile[32][33];
    const int h = blockIdx.z;
    const int c0 = blockIdx.x * 32, d0 = blockIdx.y * 32;
    const int tx = threadIdx.x, ty = threadIdx.y;
    tile[ty][tx] = wkvb[((long)h * 256 + d0 + ty) * LORA_ + c0 + tx];
    __syncthreads();
    float v = tile[tx][ty];  // [d][c] -> out[c][d]
    __nv_bfloat16 hh, ll;
    split2(v, hh, ll);
    long o = (long)h * LORA_ * NOPE_ + (long)(c0 + ty) * NOPE_ + d0 + tx;
    hi[o] = hh; lo[o] = ll;
}

// transpose keff cols 0..511: out[c][t] = in[t][c]. grid(64,16), block(32,32)
__global__ void transT_bf16(const __nv_bfloat16* __restrict__ in,
                            __nv_bfloat16* __restrict__ out)
{
    __shared__ __nv_bfloat16 tile[32][33];
    const int t0 = blockIdx.x * 32, c0 = blockIdx.y * 32;
    const int tx = threadIdx.x, ty = threadIdx.y;
    tile[ty][tx] = in[(long)(t0 + ty) * KVW_ + c0 + tx];
    __syncthreads();
    out[(long)(c0 + ty) * S_ + t0 + tx] = tile[tx][ty];
}

// rmsnorm(kv_c)+rope(k_pe) -> keff hi/lo ; rope(q_pe) -> qeff cols 512..575
__global__ void prep_kernel(const float* __restrict__ qc,
                            const float* __restrict__ cosb,
                            const float* __restrict__ sinb,
                            const float* __restrict__ knw,
                            __nv_bfloat16* __restrict__ keffhi,
                            __nv_bfloat16* __restrict__ kefflo,
                            __nv_bfloat16* __restrict__ qeffhi,
                            __nv_bfloat16* __restrict__ qefflo)
{
    const int s = blockIdx.x;
    const int tid = threadIdx.x;
    const float* kvrow = qc + (long)s * NQKV_ + 3072;
    __shared__ float red[256];

    float ss = 0.f;
    for (int c = tid; c < LORA_; c += 256) { float v = kvrow[c]; ss += v * v; }
    red[tid] = ss;
    __syncthreads();
    for (int w = 128; w > 0; w >>= 1) {
        if (tid < w) red[tid] += red[tid + w];
        __syncthreads();
    }
    float r = rsqrtf(red[0] / (float)LORA_ + 1e-6f);
    for (int c = tid; c < LORA_; c += 256) {
        __nv_bfloat16 h, l;
        split2(kvrow[c] * r * knw[c], h, l);
        keffhi[(long)s * KVW_ + c] = h;
        kefflo[(long)s * KVW_ + c] = l;
    }

    const float* cs = cosb + s * (ROPE_ / 2);
    const float* sn = sinb + s * (ROPE_ / 2);

    if (tid < 32) {
        int i = tid;
        float x0 = kvrow[LORA_ + 2 * i], x1 = kvrow[LORA_ + 2 * i + 1];
        __nv_bfloat16 h, l;
        split2(x0 * cs[i] - x1 * sn[i], h, l);
        keffhi[(long)s * KVW_ + LORA_ + 2 * i] = h;
        kefflo[(long)s * KVW_ + LORA_ + 2 * i] = l;
        split2(x0 * sn[i] + x1 * cs[i], h, l);
        keffhi[(long)s * KVW_ + LORA_ + 2 * i + 1] = h;
        kefflo[(long)s * KVW_ + LORA_ + 2 * i + 1] = l;
    }

    for (int idx = tid; idx < H_ * 32; idx += 256) {
        int h = idx >> 5, i = idx & 31;
        const float* qrow = qc + (long)s * NQKV_ + h * QKH_ + NOPE_;
        float x0 = qrow[2 * i], x1 = qrow[2 * i + 1];
        long base = ((long)h * S_ + s) * KVW_ + LORA_;
        __nv_bfloat16 hh, ll;
        split2(x0 * cs[i] - x1 * sn[i], hh, ll);
        qeffhi[base + 2 * i] = hh; qefflo[base + 2 * i] = ll;
        split2(x0 * sn[i] + x1 * cs[i], hh, ll);
        qeffhi[base + 2 * i + 1] = hh; qefflo[base + 2 * i + 1] = ll;
    }
}

// causal softmax in place over scores stored as bf16 hi/lo (attn arrays).
// Thread t owns 8 contiguous cols; uint4 reads of hi+lo, bf162 stores.
// Zero-fill only to the 128-aligned diagonal tile boundary.
__global__ void softmax_kernel(__nv_bfloat16* __restrict__ attnhi,
                               __nv_bfloat16* __restrict__ attnlo)
{
    const int s = blockIdx.x, h = blockIdx.y;
    __nv_bfloat16* ohi = attnhi + ((long)h * S_ + s) * S_;
    __nv_bfloat16* olo = attnlo + ((long)h * S_ + s) * S_;
    const int n = s + 1;
    const int nz = ((s >> 7) + 1) << 7;   // round up to 128
    const int tid = threadIdx.x;
    const int lane = tid & 31, wid = tid >> 5;
    const int c0 = tid * 8;
    __shared__ float wred[8];

    float vals[8];
    float m = -1e30f;
    if (c0 < nz) {
        uint4 hv = *(const uint4*)(ohi + c0);
        uint4 lv = *(const uint4*)(olo + c0);
        const __nv_bfloat162* hp = (const __nv_bfloat162*)&hv;
        const __nv_bfloat162* lp = (const __nv_bfloat162*)&lv;
#pragma unroll
        for (int j = 0; j < 4; j++) {
            float2 hf = __bfloat1622float2(hp[j]);
            float2 lf = __bfloat1622float2(lp[j]);
            vals[2 * j]     = hf.x + lf.x;
            vals[2 * j + 1] = hf.y + lf.y;
        }
#pragma unroll
        for (int j = 0; j < 8; j++)
            if (c0 + j < n) m = fmaxf(m, vals[j]);
    }
#pragma unroll
    for (int o = 16; o > 0; o >>= 1)
        m = fmaxf(m, __shfl_xor_sync(0xffffffffu, m, o));
    if (lane == 0) wred[wid] = m;
    __syncthreads();
    m = -1e30f;
#pragma unroll
    for (int w = 0; w < 8; w++) m = fmaxf(m, wred[w]);
    __syncthreads();

    float sum = 0.f;
    if (c0 < nz) {
#pragma unroll
        for (int j = 0; j < 8; j++) {
            float e = (c0 + j < n) ? __expf(vals[j] - m) : 0.f;
            vals[j] = e;
            sum += e;
        }
    }
#pragma unroll
    for (int o = 16; o > 0; o >>= 1)
        sum += __shfl_xor_sync(0xffffffffu, sum, o);
    if (lane == 0) wred[wid] = sum;
    __syncthreads();
    sum = 0.f;
#pragma unroll
    for (int w = 0; w < 8; w++) sum += wred[w];
    float inv = 1.0f / sum;

    if (c0 < nz) {
        __nv_bfloat162 hv[4], lv[4];
#pragma unroll
        for (int j = 0; j < 4; j++) {
            __nv_bfloat16 h0, h1, l0, l1;
            split2(vals[2 * j] * inv, h0, l0);
            split2(vals[2 * j + 1] * inv, h1, l1);
            hv[j] = __nv_bfloat162(h0, h1);
            lv[j] = __nv_bfloat162(l0, l1);
        }
        *(uint4*)(ohi + c0) = *(uint4*)hv;
        *(uint4*)(olo + c0) = *(uint4*)lv;
    }
}

// ---------------------------------------------------------------------------
// Launch
// ---------------------------------------------------------------------------
extern "C" void kernel_launch(void* const* d_in, const int* in_sizes, int n_in,
                              void* d_out, int out_size)
{
    const float* x     = (const float*)d_in[0];
    const float* cosb  = (const float*)d_in[1];
    const float* sinb  = (const float*)d_in[2];
    const float* wq    = (const float*)d_in[3];
    const float* wkv_a = (const float*)d_in[4];
    const float* knw   = (const float*)d_in[5];
    const float* wkv_b = (const float*)d_in[6];
    const float* wo    = (const float*)d_in[7];
    float* out = (float*)d_out;

    cudaFuncSetAttribute(tgemm, cudaFuncAttributeMaxDynamicSharedMemorySize,
                         DSMEM_BYTES);

    float *qc;
    cudaGetSymbolAddress((void**)&qc, d_qc);

    __nv_bfloat16 *xhi,*xlo,*wqkvhi,*wqkvlo,*wohi,*wolo;
    __nv_bfloat16 *wkvbhi,*wkvblo,*wukThi,*wukTlo,*qchi,*qclo;
    __nv_bfloat16 *qeffhi,*qefflo,*keffhi,*kefflo,*keffThi,*keffTlo;
    __nv_bfloat16 *attnhi,*attnlo,*o1hi,*o1lo,*o2hi,*o2lo;
    cudaGetSymbolAddress((void**)&xhi, d_xhi);       cudaGetSymbolAddress((void**)&xlo, d_xlo);
    cudaGetSymbolAddress((void**)&wqkvhi, d_wqkvhi); cudaGetSymbolAddress((void**)&wqkvlo, d_wqkvlo);
    cudaGetSymbolAddress((void**)&wohi, d_wohi);     cudaGetSymbolAddress((void**)&wolo, d_wolo);
    cudaGetSymbolAddress((void**)&wkvbhi, d_wkvbhi); cudaGetSymbolAddress((void**)&wkvblo, d_wkvblo);
    cudaGetSymbolAddress((void**)&wukThi, d_wukThi); cudaGetSymbolAddress((void**)&wukTlo, d_wukTlo);
    cudaGetSymbolAddress((void**)&qchi, d_qchi);     cudaGetSymbolAddress((void**)&qclo, d_qclo);
    cudaGetSymbolAddress((void**)&qeffhi, d_qeffhi); cudaGetSymbolAddress((void**)&qefflo, d_qefflo);
    cudaGetSymbolAddress((void**)&keffhi, d_keffhi); cudaGetSymbolAddress((void**)&kefflo, d_kefflo);
    cudaGetSymbolAddress((void**)&keffThi, d_keffThi); cudaGetSymbolAddress((void**)&keffTlo, d_keffTlo);
    cudaGetSymbolAddress((void**)&attnhi, d_attnhi); cudaGetSymbolAddress((void**)&attnlo, d_attnlo);
    cudaGetSymbolAddress((void**)&o1hi, d_o1hi);     cudaGetSymbolAddress((void**)&o1lo, d_o1lo);
    cudaGetSymbolAddress((void**)&o2hi, d_o2hi);     cudaGetSymbolAddress((void**)&o2lo, d_o2lo);

    // -------- operand splits --------
    {
        long n4;
        n4 = (long)S_ * DIM_ / 4;
        split_kernel<<<(n4 + 255) / 256, 256>>>(
            (const float4*)x, (__nv_bfloat162*)xhi, (__nv_bfloat162*)xlo, n4);
        n4 = (long)NQKV_ * DIM_ / 4;
        split_concat_wqkv<<<(n4 + 255) / 256, 256>>>(
            (const float4*)wq, (const float4*)wkv_a,
            (__nv_bfloat162*)wqkvhi, (__nv_bfloat162*)wqkvlo);
        n4 = (long)DIM_ * DIM_ / 4;
        split_kernel<<<(n4 + 255) / 256, 256>>>(
            (const float4*)wo, (__nv_bfloat162*)wohi, (__nv_bfloat162*)wolo, n4);
        n4 = (long)H_ * 256 * LORA_ / 4;
        split_kernel<<<(n4 + 255) / 256, 256>>>(
            (const float4*)wkv_b, (__nv_bfloat162*)wkvbhi, (__nv_bfloat162*)wkvblo, n4);
        wukt_kernel<<<dim3(16, 4, 16), dim3(32, 32)>>>(wkv_b, wukThi, wukTlo);
    }

    // 1. [q | kv] = x @ [wq | wkv_a]^T  (2048 x 3712), f32 + hi/lo
    tgemm<<<dim3(NQKV_ / 128, 16, 1), 256, DSMEM_BYTES>>>(
        xhi, xlo, 0, DIM_, wqkvhi, wqkvlo, 0, DIM_,
        qc, qchi, qclo, 0, NQKV_, DIM_, 1.f, 0);

    // 2. prep: rmsnorm + rope
    prep_kernel<<<S_, 256>>>(qc, cosb, sinb, knw,
                             keffhi, kefflo, qeffhi, qefflo);

    // 3. q_c[h] -> qeff cols 0..511 (hi/lo)
    tgemm<<<dim3(LORA_ / 128, 16, H_), 256, DSMEM_BYTES>>>(
        qchi, qclo, (long)QKH_, NQKV_, wukThi, wukTlo, (long)LORA_ * NOPE_, NOPE_,
        nullptr, qeffhi, qefflo, (long)S_ * KVW_, KVW_, NOPE_, 1.f, 0);

    // 4. keffT (cols 0..511 transposed)
    transT_bf16<<<dim3(64, 16), dim3(32, 32)>>>(keffhi, keffThi);
    transT_bf16<<<dim3(64, 16), dim3(32, 32)>>>(kefflo, keffTlo);

    // 5. scores[h] = SCALE * qeff[h] @ keff^T -> bf16 hi/lo (in attn arrays)
    tgemm<<<dim3(16, 16, H_), 256, DSMEM_BYTES>>>(
        qeffhi, qefflo, (long)S_ * KVW_, KVW_, keffhi, kefflo, 0, KVW_,
        nullptr, attnhi, attnlo, (long)S_ * S_, S_, KVW_, SCALE_, 1);

    // 6. softmax in place on attn hi/lo
    softmax_kernel<<<dim3(S_, H_), 256>>>(attnhi, attnlo);

    // 7. o1[h] = attn[h] @ kv_c  (B = keffT, K limited to diagonal)
    tgemm<<<dim3(LORA_ / 128, 16, H_), 256, DSMEM_BYTES>>>(
        attnhi, attnlo, (long)S_ * S_, S_, keffThi, keffTlo, 0, S_,
        nullptr, o1hi, o1lo, (long)S_ * LORA_, LORA_, S_, 1.f, 2);

    // 8. o2[:, h*128:+128] = o1[h] @ w_uv[h]^T
    tgemm<<<dim3(1, 16, H_), 256, DSMEM_BYTES>>>(
        o1hi, o1lo, (long)S_ * LORA_, LORA_,
        wkvbhi + (long)NOPE_ * LORA_, wkvblo + (long)NOPE_ * LORA_,
        (long)256 * LORA_, LORA_,
        nullptr, o2hi, o2lo, (long)VD_, DIM_, LORA_, 1.f, 0);

    // 9. out = o2 @ wo^T
    tgemm<<<dim3(16, 16, 1), 256, DSMEM_BYTES>>>(
        o2hi, o2lo, 0, DIM_, wohi, wolo, 0, DIM_,
        out, nullptr, nullptr, 0, DIM_, DIM_, 1.f, 0);
}

// round 9
// speedup vs baseline: 1.4708x; 1.4708x over previous
#include <cuda_runtime.h>
#include <cuda_bf16.h>
#include <cstdint>

// ---------------------------------------------------------------------------
// Problem constants
// ---------------------------------------------------------------------------
#define S_ 2048
#define DIM_ 2048
#define H_ 16
#define NOPE_ 128
#define ROPE_ 64
#define VD_ 128
#define LORA_ 512
#define QKH_ 192            // NOPE + ROPE
#define KVW_ 576            // LORA + ROPE
#define NQKV_ 3712          // 3072 (q) + 640 (kv padded)
#define KQK_ 192            // per-head qk dim after reassociation
#define SCALE_ 0.07216878364870323f  // 192^-0.5

// ---------------------------------------------------------------------------
// Scratch
// ---------------------------------------------------------------------------
__device__ __nv_bfloat16 d_xhi[(long)S_ * DIM_],      d_xlo[(long)S_ * DIM_];
__device__ __nv_bfloat16 d_wqkvhi[(long)NQKV_ * DIM_],d_wqkvlo[(long)NQKV_ * DIM_];
__device__ __nv_bfloat16 d_wohi[(long)DIM_ * DIM_],   d_wolo[(long)DIM_ * DIM_];
__device__ __nv_bfloat16 d_wkvbhi[(long)H_ * 256 * LORA_], d_wkvblo[(long)H_ * 256 * LORA_];
__device__ __nv_bfloat16 d_qchi[(long)S_ * NQKV_],    d_qclo[(long)S_ * NQKV_];   // q roped in place
__device__ __nv_bfloat16 d_keffhi[(long)S_ * LORA_],  d_kefflo[(long)S_ * LORA_]; // normed kv_c
__device__ __nv_bfloat16 d_kfullhi[(long)H_ * S_ * KQK_], d_kfulllo[(long)H_ * S_ * KQK_]; // [k_nope | k_pe]
__device__ __nv_bfloat16 d_vThi[(long)H_ * VD_ * S_], d_vTlo[(long)H_ * VD_ * S_];
__device__ __nv_bfloat16 d_attnhi[(long)H_ * S_ * S_],d_attnlo[(long)H_ * S_ * S_];
__device__ __nv_bfloat16 d_o2hi[(long)S_ * DIM_],     d_o2lo[(long)S_ * DIM_];

// ---------------------------------------------------------------------------
// Helpers
// ---------------------------------------------------------------------------
__device__ __forceinline__ uint32_t smem_u32(const void* p) {
    uint32_t a;
    asm("{ .reg .u64 t; cvta.to.shared.u64 t, %1; cvt.u32.u64 %0, t; }"
        : "=r"(a) : "l"(p));
    return a;
}

__device__ __forceinline__ void ldsm_x4(uint32_t* r, uint32_t addr) {
    asm volatile("ldmatrix.sync.aligned.m8n8.x4.shared.b16 {%0,%1,%2,%3}, [%4];"
                 : "=r"(r[0]), "=r"(r[1]), "=r"(r[2]), "=r"(r[3]) : "r"(addr));
}
__device__ __forceinline__ void ldsm_x2(uint32_t* r, uint32_t addr) {
    asm volatile("ldmatrix.sync.aligned.m8n8.x2.shared.b16 {%0,%1}, [%2];"
                 : "=r"(r[0]), "=r"(r[1]) : "r"(addr));
}
__device__ __forceinline__ void mma16816(float* c, const uint32_t* a, const uint32_t* b) {
    asm volatile(
        "mma.sync.aligned.m16n8k16.row.col.f32.bf16.bf16.f32 "
        "{%0,%1,%2,%3}, {%4,%5,%6,%7}, {%8,%9}, {%0,%1,%2,%3};"
        : "+f"(c[0]), "+f"(c[1]), "+f"(c[2]), "+f"(c[3])
        : "r"(a[0]), "r"(a[1]), "r"(a[2]), "r"(a[3]), "r"(b[0]), "r"(b[1]));
}

__device__ __forceinline__ void split2(float v, __nv_bfloat16& h, __nv_bfloat16& l) {
    h = __float2bfloat16(v);
    l = __float2bfloat16(v - __bfloat162float(h));
}
__device__ __forceinline__ float rec2(__nv_bfloat16 h, __nv_bfloat16 l) {
    return __bfloat162float(h) + __bfloat162float(l);
}

// ---------------------------------------------------------------------------
// bf16 split-precision GEMM via mma.sync (R7-proven mainloop):
//   C(z) = alpha * A(z)(M,K) @ B(z)(N,K)^T
//   C ~= Ahi.Bhi + Ahi.Blo + Alo.Bhi  (fp32 accum)
// CTA tile 128x128, K chunk 32, cp.async double buffer, 2 CTAs/SM.
// SMEM: 128 rows x 80B pitch -> conflict-free ldmatrix.
// grid = (N/128, M/128, Z); 256 threads (8 warps, warp 64x32).
// causal: 1 = skip tiles with bx > by; 2 = Klim = min(K, row0+128)
// ---------------------------------------------------------------------------
#define TILE_B 10240            // 128 * 80
#define STAGE_B 40960           // 4 tiles
#define DSMEM_BYTES 81920       // 2 stages

__device__ __forceinline__ void load_tile32(uint32_t dst,
                                            const __nv_bfloat16* __restrict__ src,
                                            int rbase, int ld, int k0, int tid)
{
#pragma unroll
    for (int t = 0; t < 2; t++) {
        int o = tid + t * 256;          // 0..511 : 128 rows x 4 x 16B
        int row = o >> 2, c = o & 3;
        const void* g = (const void*)(src + (long)(rbase + row) * ld + k0 + c * 8);
        asm volatile("cp.async.cg.shared.global [%0], [%1], 16;"
                     :: "r"(dst + row * 80 + c * 16), "l"(g));
    }
}

__global__ void __launch_bounds__(256, 2)
tgemm(const __nv_bfloat16* __restrict__ Ahi, const __nv_bfloat16* __restrict__ Alo,
      long sA, int lda,
      const __nv_bfloat16* __restrict__ Bhi, const __nv_bfloat16* __restrict__ Blo,
      long sB, int ldb,
      float* Cf, __nv_bfloat16* Chi, __nv_bfloat16* Clo,
      long sC, int ldc,
      int K, float alpha, int causal)
{
    const int bx = blockIdx.x, by = blockIdx.y, z = blockIdx.z;
    if (causal == 1 && bx > by) return;
    const int row0 = by * 128, col0 = bx * 128;
    int Klim = (causal == 2) ? min(K, row0 + 128) : K;
    const int nc = Klim >> 5;

    Ahi += (long)z * sA;  Alo += (long)z * sA;
    Bhi += (long)z * sB;  Blo += (long)z * sB;
    if (Cf)  Cf  += (long)z * sC;
    if (Chi) { Chi += (long)z * sC; Clo += (long)z * sC; }

    extern __shared__ char dsm[];
    const uint32_t s0 = smem_u32(dsm);

    const int tid = threadIdx.x;
    const int lane = tid & 31;
    const int wid = tid >> 5;
    const int wm = wid & 1;          // 0..1  (M)
    const int wn = wid >> 1;         // 0..3  (N)

    float acc[4][4][4];
#pragma unroll
    for (int mt = 0; mt < 4; mt++)
#pragma unroll
        for (int nt = 0; nt < 4; nt++)
#pragma unroll
            for (int e = 0; e < 4; e++) acc[mt][nt][e] = 0.f;

    // prologue: fill stage 0
    {
        uint32_t sb = s0;
        load_tile32(sb,              Ahi, row0, lda, 0, tid);
        load_tile32(sb + TILE_B,     Alo, row0, lda, 0, tid);
        load_tile32(sb + 2 * TILE_B, Bhi, col0, ldb, 0, tid);
        load_tile32(sb + 3 * TILE_B, Blo, col0, ldb, 0, tid);
        asm volatile("cp.async.commit_group;" ::: "memory");
    }

    const uint32_t a_off = (wm * 64 + (lane & 15)) * 80 + ((lane >> 4) << 4);
    const uint32_t b_off = (wn * 32 + (lane & 7)) * 80 + (((lane >> 3) & 1) << 4);

    for (int i = 0; i < nc; i++) {
        if (i + 1 < nc) {
            uint32_t sb = s0 + ((i + 1) & 1) * STAGE_B;
            int k0 = (i + 1) << 5;
            load_tile32(sb,              Ahi, row0, lda, k0, tid);
            load_tile32(sb + TILE_B,     Alo, row0, lda, k0, tid);
            load_tile32(sb + 2 * TILE_B, Bhi, col0, ldb, k0, tid);
            load_tile32(sb + 3 * TILE_B, Blo, col0, ldb, k0, tid);
            asm volatile("cp.async.commit_group;" ::: "memory");
            asm volatile("cp.async.wait_group 1;" ::: "memory");
        } else {
            asm volatile("cp.async.wait_group 0;" ::: "memory");
        }
        __syncthreads();

        const uint32_t sb = s0 + (i & 1) * STAGE_B;
#pragma unroll
        for (int ks = 0; ks < 2; ks++) {
            const uint32_t kb = ks * 32;
            uint32_t bh[4][2], bl[4][2];
#pragma unroll
            for (int nt = 0; nt < 4; nt++) {
                ldsm_x2(bh[nt], sb + 2 * TILE_B + b_off + nt * (8 * 80) + kb);
                ldsm_x2(bl[nt], sb + 3 * TILE_B + b_off + nt * (8 * 80) + kb);
            }
#pragma unroll
            for (int mt = 0; mt < 4; mt++) {
                uint32_t ah[4], al[4];
                ldsm_x4(ah, sb + a_off + mt * (16 * 80) + kb);
                ldsm_x4(al, sb + TILE_B + a_off + mt * (16 * 80) + kb);
#pragma unroll
                for (int nt = 0; nt < 4; nt++) {
                    mma16816(acc[mt][nt], ah, bh[nt]);
                    mma16816(acc[mt][nt], ah, bl[nt]);
                    mma16816(acc[mt][nt], al, bh[nt]);
                }
            }
        }
        __syncthreads();
    }

    // ---------------- epilogue: stage through smem ----------------
    float* stage = (float*)dsm;   // pitch 132 f32: 128*132*4 = 67584 <= 81920
#pragma unroll
    for (int mt = 0; mt < 4; mt++) {
        int r = wm * 64 + mt * 16 + (lane >> 2);
#pragma unroll
        for (int nt = 0; nt < 4; nt++) {
            int c = wn * 32 + nt * 8 + (lane & 3) * 2;
            stage[r * 132 + c]           = acc[mt][nt][0] * alpha;
            stage[r * 132 + c + 1]       = acc[mt][nt][1] * alpha;
            stage[(r + 8) * 132 + c]     = acc[mt][nt][2] * alpha;
            stage[(r + 8) * 132 + c + 1] = acc[mt][nt][3] * alpha;
        }
    }
    __syncthreads();

#pragma unroll
    for (int it = 0; it < 16; it++) {
        int g = tid + it * 256;
        int m = g >> 5, cg = (g & 31) * 4;
        float v0 = stage[m * 132 + cg + 0];
        float v1 = stage[m * 132 + cg + 1];
        float v2 = stage[m * 132 + cg + 2];
        float v3 = stage[m * 132 + cg + 3];
        long off = (long)(row0 + m) * ldc + col0 + cg;
        if (Cf) {
            float4 v = make_float4(v0, v1, v2, v3);
            *(float4*)(Cf + off) = v;
        }
        if (Chi) {
            __nv_bfloat16 h0, h1, h2, h3, l0, l1, l2, l3;
            split2(v0, h0, l0); split2(v1, h1, l1);
            split2(v2, h2, l2); split2(v3, h3, l3);
            *(__nv_bfloat162*)(Chi + off)     = __nv_bfloat162(h0, h1);
            *(__nv_bfloat162*)(Chi + off + 2) = __nv_bfloat162(h2, h3);
            *(__nv_bfloat162*)(Clo + off)     = __nv_bfloat162(l0, l1);
            *(__nv_bfloat162*)(Clo + off + 2) = __nv_bfloat162(l2, l3);
        }
    }
}

// ---------------------------------------------------------------------------
// Pointwise / prep kernels
// ---------------------------------------------------------------------------
__global__ void split_kernel(const float4* __restrict__ in,
                             __nv_bfloat162* __restrict__ hi,
                             __nv_bfloat162* __restrict__ lo, long n4)
{
    long i = (long)blockIdx.x * blockDim.x + threadIdx.x;
    if (i < n4) {
        float4 v = in[i];
        __nv_bfloat16 h0, h1, h2, h3, l0, l1, l2, l3;
        split2(v.x, h0, l0); split2(v.y, h1, l1);
        split2(v.z, h2, l2); split2(v.w, h3, l3);
        hi[2 * i]     = __nv_bfloat162(h0, h1);
        hi[2 * i + 1] = __nv_bfloat162(h2, h3);
        lo[2 * i]     = __nv_bfloat162(l0, l1);
        lo[2 * i + 1] = __nv_bfloat162(l2, l3);
    }
}

// concat wq (3072x2048) + wkv_a (576x2048, zero-padded to 640) -> 3712x2048
__global__ void split_concat_wqkv(const float4* __restrict__ wq,
                                  const float4* __restrict__ wkva,
                                  __nv_bfloat162* __restrict__ hi,
                                  __nv_bfloat162* __restrict__ lo)
{
    long i = (long)blockIdx.x * blockDim.x + threadIdx.x;  // float4 index
    long n4 = (long)NQKV_ * DIM_ / 4;
    if (i < n4) {
        long r = i / (DIM_ / 4);
        float4 v;
        if (r < 3072)             v = wq[i];
        else if (r < 3072 + KVW_) v = wkva[i - (long)3072 * (DIM_ / 4)];
        else                      v = make_float4(0.f, 0.f, 0.f, 0.f);
        __nv_bfloat16 h0, h1, h2, h3, l0, l1, l2, l3;
        split2(v.x, h0, l0); split2(v.y, h1, l1);
        split2(v.z, h2, l2); split2(v.w, h3, l3);
        hi[2 * i]     = __nv_bfloat162(h0, h1);
        hi[2 * i + 1] = __nv_bfloat162(h2, h3);
        lo[2 * i]     = __nv_bfloat162(l0, l1);
        lo[2 * i + 1] = __nv_bfloat162(l2, l3);
    }
}

// rmsnorm(kv_c) -> keff hi/lo ; rope(k_pe) -> kfull cols 128..191 (all heads);
// rope(q_pe) in place in qchi/qclo. qc layout: [q(3072) | kv(640)] per row.
__global__ void prep_kernel(__nv_bfloat16* __restrict__ qchi,
                            __nv_bfloat16* __restrict__ qclo,
                            const float* __restrict__ cosb,
                            const float* __restrict__ sinb,
                            const float* __restrict__ knw,
                            __nv_bfloat16* __restrict__ keffhi,
                            __nv_bfloat16* __restrict__ kefflo,
                            __nv_bfloat16* __restrict__ kfullhi,
                            __nv_bfloat16* __restrict__ kfulllo)
{
    const int s = blockIdx.x;
    const int tid = threadIdx.x;
    __nv_bfloat16* kvhi = qchi + (long)s * NQKV_ + 3072;
    __nv_bfloat16* kvlo = qclo + (long)s * NQKV_ + 3072;
    __shared__ float red[256];

    // rmsnorm over kv_c (512)
    float ss = 0.f;
    for (int c = tid; c < LORA_; c += 256) {
        float v = rec2(kvhi[c], kvlo[c]);
        ss += v * v;
    }
    red[tid] = ss;
    __syncthreads();
    for (int w = 128; w > 0; w >>= 1) {
        if (tid < w) red[tid] += red[tid + w];
        __syncthreads();
    }
    float r = rsqrtf(red[0] / (float)LORA_ + 1e-6f);
    for (int c = tid; c < LORA_; c += 256) {
        float v = rec2(kvhi[c], kvlo[c]);
        __nv_bfloat16 h, l;
        split2(v * r * knw[c], h, l);
        keffhi[(long)s * LORA_ + c] = h;
        kefflo[(long)s * LORA_ + c] = l;
    }

    const float* cs = cosb + s * (ROPE_ / 2);
    const float* sn = sinb + s * (ROPE_ / 2);

    // rope k_pe -> kfull[h][s][128+...] for all 16 heads
    for (int idx = tid; idx < H_ * 32; idx += 256) {
        int h = idx >> 5, i = idx & 31;
        float x0 = rec2(kvhi[LORA_ + 2 * i], kvlo[LORA_ + 2 * i]);
        float x1 = rec2(kvhi[LORA_ + 2 * i + 1], kvlo[LORA_ + 2 * i + 1]);
        float y0 = x0 * cs[i] - x1 * sn[i];
        float y1 = x0 * sn[i] + x1 * cs[i];
        long base = ((long)h * S_ + s) * KQK_ + NOPE_;
        __nv_bfloat16 hh, ll;
        split2(y0, hh, ll);
        kfullhi[base + 2 * i] = hh; kfulllo[base + 2 * i] = ll;
        split2(y1, hh, ll);
        kfullhi[base + 2 * i + 1] = hh; kfulllo[base + 2 * i + 1] = ll;
    }

    // rope q_pe in place (per head cols h*192+128 .. +191)
    for (int idx = tid; idx < H_ * 32; idx += 256) {
        int h = idx >> 5, i = idx & 31;
        long base = (long)s * NQKV_ + h * QKH_ + NOPE_;
        float x0 = rec2(qchi[base + 2 * i], qclo[base + 2 * i]);
        float x1 = rec2(qchi[base + 2 * i + 1], qclo[base + 2 * i + 1]);
        float y0 = x0 * cs[i] - x1 * sn[i];
        float y1 = x0 * sn[i] + x1 * cs[i];
        __nv_bfloat16 hh, ll;
        split2(y0, hh, ll);
        qchi[base + 2 * i] = hh; qclo[base + 2 * i] = ll;
        split2(y1, hh, ll);
        qchi[base + 2 * i + 1] = hh; qclo[base + 2 * i + 1] = ll;
    }
}

// causal softmax in place over scores stored as bf16 hi/lo (attn arrays).
// Thread t owns 8 contiguous cols; uint4 reads of hi+lo, bf162 stores.
// Zero-fill only to the 128-aligned diagonal tile boundary.
__global__ void softmax_kernel(__nv_bfloat16* __restrict__ attnhi,
                               __nv_bfloat16* __restrict__ attnlo)
{
    const int s = blockIdx.x, h = blockIdx.y;
    __nv_bfloat16* ohi = attnhi + ((long)h * S_ + s) * S_;
    __nv_bfloat16* olo = attnlo + ((long)h * S_ + s) * S_;
    const int n = s + 1;
    const int nz = ((s >> 7) + 1) << 7;   // round up to 128
    const int tid = threadIdx.x;
    const int lane = tid & 31, wid = tid >> 5;
    const int c0 = tid * 8;
    __shared__ float wred[8];

    float vals[8];
    float m = -1e30f;
    if (c0 < nz) {
        uint4 hv = *(const uint4*)(ohi + c0);
        uint4 lv = *(const uint4*)(olo + c0);
        const __nv_bfloat162* hp = (const __nv_bfloat162*)&hv;
        const __nv_bfloat162* lp = (const __nv_bfloat162*)&lv;
#pragma unroll
        for (int j = 0; j < 4; j++) {
            float2 hf = __bfloat1622float2(hp[j]);
            float2 lf = __bfloat1622float2(lp[j]);
            vals[2 * j]     = hf.x + lf.x;
            vals[2 * j + 1] = hf.y + lf.y;
        }
#pragma unroll
        for (int j = 0; j < 8; j++)
            if (c0 + j < n) m = fmaxf(m, vals[j]);
    }
#pragma unroll
    for (int o = 16; o > 0; o >>= 1)
        m = fmaxf(m, __shfl_xor_sync(0xffffffffu, m, o));
    if (lane == 0) wred[wid] = m;
    __syncthreads();
    m = -1e30f;
#pragma unroll
    for (int w = 0; w < 8; w++) m = fmaxf(m, wred[w]);
    __syncthreads();

    float sum = 0.f;
    if (c0 < nz) {
#pragma unroll
        for (int j = 0; j < 8; j++) {
            float e = (c0 + j < n) ? __expf(vals[j] - m) : 0.f;
            vals[j] = e;
            sum += e;
        }
    }
#pragma unroll
    for (int o = 16; o > 0; o >>= 1)
        sum += __shfl_xor_sync(0xffffffffu, sum, o);
    if (lane == 0) wred[wid] = sum;
    __syncthreads();
    sum = 0.f;
#pragma unroll
    for (int w = 0; w < 8; w++) sum += wred[w];
    float inv = 1.0f / sum;

    if (c0 < nz) {
        __nv_bfloat162 hv[4], lv[4];
#pragma unroll
        for (int j = 0; j < 4; j++) {
            __nv_bfloat16 h0, h1, l0, l1;
            split2(vals[2 * j] * inv, h0, l0);
            split2(vals[2 * j + 1] * inv, h1, l1);
            hv[j] = __nv_bfloat162(h0, h1);
            lv[j] = __nv_bfloat162(l0, l1);
        }
        *(uint4*)(ohi + c0) = *(uint4*)hv;
        *(uint4*)(olo + c0) = *(uint4*)lv;
    }
}

// ---------------------------------------------------------------------------
// Launch
// ---------------------------------------------------------------------------
extern "C" void kernel_launch(void* const* d_in, const int* in_sizes, int n_in,
                              void* d_out, int out_size)
{
    const float* x     = (const float*)d_in[0];
    const float* cosb  = (const float*)d_in[1];
    const float* sinb  = (const float*)d_in[2];
    const float* wq    = (const float*)d_in[3];
    const float* wkv_a = (const float*)d_in[4];
    const float* knw   = (const float*)d_in[5];
    const float* wkv_b = (const float*)d_in[6];
    const float* wo    = (const float*)d_in[7];
    float* out = (float*)d_out;

    cudaFuncSetAttribute(tgemm, cudaFuncAttributeMaxDynamicSharedMemorySize,
                         DSMEM_BYTES);

    __nv_bfloat16 *xhi,*xlo,*wqkvhi,*wqkvlo,*wohi,*wolo,*wkvbhi,*wkvblo;
    __nv_bfloat16 *qchi,*qclo,*keffhi,*kefflo,*kfullhi,*kfulllo;
    __nv_bfloat16 *vThi,*vTlo,*attnhi,*attnlo,*o2hi,*o2lo;
    cudaGetSymbolAddress((void**)&xhi, d_xhi);       cudaGetSymbolAddress((void**)&xlo, d_xlo);
    cudaGetSymbolAddress((void**)&wqkvhi, d_wqkvhi); cudaGetSymbolAddress((void**)&wqkvlo, d_wqkvlo);
    cudaGetSymbolAddress((void**)&wohi, d_wohi);     cudaGetSymbolAddress((void**)&wolo, d_wolo);
    cudaGetSymbolAddress((void**)&wkvbhi, d_wkvbhi); cudaGetSymbolAddress((void**)&wkvblo, d_wkvblo);
    cudaGetSymbolAddress((void**)&qchi, d_qchi);     cudaGetSymbolAddress((void**)&qclo, d_qclo);
    cudaGetSymbolAddress((void**)&keffhi, d_keffhi); cudaGetSymbolAddress((void**)&kefflo, d_kefflo);
    cudaGetSymbolAddress((void**)&kfullhi, d_kfullhi); cudaGetSymbolAddress((void**)&kfulllo, d_kfulllo);
    cudaGetSymbolAddress((void**)&vThi, d_vThi);     cudaGetSymbolAddress((void**)&vTlo, d_vTlo);
    cudaGetSymbolAddress((void**)&attnhi, d_attnhi); cudaGetSymbolAddress((void**)&attnlo, d_attnlo);
    cudaGetSymbolAddress((void**)&o2hi, d_o2hi);     cudaGetSymbolAddress((void**)&o2lo, d_o2lo);

    // -------- operand splits --------
    {
        long n4;
        n4 = (long)S_ * DIM_ / 4;
        split_kernel<<<(n4 + 255) / 256, 256>>>(
            (const float4*)x, (__nv_bfloat162*)xhi, (__nv_bfloat162*)xlo, n4);
        n4 = (long)NQKV_ * DIM_ / 4;
        split_concat_wqkv<<<(n4 + 255) / 256, 256>>>(
            (const float4*)wq, (const float4*)wkv_a,
            (__nv_bfloat162*)wqkvhi, (__nv_bfloat162*)wqkvlo);
        n4 = (long)DIM_ * DIM_ / 4;
        split_kernel<<<(n4 + 255) / 256, 256>>>(
            (const float4*)wo, (__nv_bfloat162*)wohi, (__nv_bfloat162*)wolo, n4);
        n4 = (long)H_ * 256 * LORA_ / 4;
        split_kernel<<<(n4 + 255) / 256, 256>>>(
            (const float4*)wkv_b, (__nv_bfloat162*)wkvbhi, (__nv_bfloat162*)wkvblo, n4);
    }

    // 1. [q | kv] = x @ [wq | wkv_a]^T  (2048 x 3712), hi/lo only
    tgemm<<<dim3(NQKV_ / 128, 16, 1), 256, DSMEM_BYTES>>>(
        xhi, xlo, 0, DIM_, wqkvhi, wqkvlo, 0, DIM_,
        nullptr, qchi, qclo, 0, NQKV_, DIM_, 1.f, 0);

    // 2. prep: rmsnorm + rope (q in place, k_pe into kfull, keff out)
    prep_kernel<<<S_, 256>>>(qchi, qclo, cosb, sinb, knw,
                             keffhi, kefflo, kfullhi, kfulllo);

    // 3. k_nope[h] = keff @ w_uk[h]^T -> kfull[h] cols 0..127
    //    A = keff (M=2048, K=512), B = wkv_b rows 0..127 of head block (N=128, K=512)
    tgemm<<<dim3(1, 16, H_), 256, DSMEM_BYTES>>>(
        keffhi, kefflo, 0, LORA_,
        wkvbhi, wkvblo, (long)256 * LORA_, LORA_,
        nullptr, kfullhi, kfulllo, (long)S_ * KQK_, KQK_, LORA_, 1.f, 0);

    // 4. vT[h] = w_uv[h] @ keff^T  (M=128 d, N=2048 t, K=512)
    tgemm<<<dim3(16, 1, H_), 256, DSMEM_BYTES>>>(
        wkvbhi + (long)NOPE_ * LORA_, wkvblo + (long)NOPE_ * LORA_,
        (long)256 * LORA_, LORA_,
        keffhi, kefflo, 0, LORA_,
        nullptr, vThi, vTlo, (long)VD_ * S_, S_, LORA_, 1.f, 0);

    // 5. scores[h] = SCALE * q[h](K=192) @ kfull[h]^T -> attn hi/lo (causal skip)
    tgemm<<<dim3(16, 16, H_), 256, DSMEM_BYTES>>>(
        qchi, qclo, (long)QKH_, NQKV_,
        kfullhi, kfulllo, (long)S_ * KQK_, KQK_,
        nullptr, attnhi, attnlo, (long)S_ * S_, S_, KQK_, SCALE_, 1);

    // 6. softmax in place on attn hi/lo
    softmax_kernel<<<dim3(S_, H_), 256>>>(attnhi, attnlo);

    // 7. o2[:, h*128:+128] = attn[h] @ vT[h]^T  (N=128, K diag-limited)
    tgemm<<<dim3(1, 16, H_), 256, DSMEM_BYTES>>>(
        attnhi, attnlo, (long)S_ * S_, S_,
        vThi, vTlo, (long)VD_ * S_, S_,
        nullptr, o2hi, o2lo, (long)VD_, DIM_, S_, 1.f, 2);

    // 8. out = o2 @ wo^T
    tgemm<<<dim3(16, 16, 1), 256, DSMEM_BYTES>>>(
        o2hi, o2lo, 0, DIM_, wohi, wolo, 0, DIM_,
        out, nullptr, nullptr, 0, DIM_, DIM_, 1.f, 0);
}

// round 10
// speedup vs baseline: 1.6711x; 1.1362x over previous
#include <cuda_runtime.h>
#include <cuda_bf16.h>
#include <cstdint>

// ---------------------------------------------------------------------------
// Problem constants
// ---------------------------------------------------------------------------
#define S_ 2048
#define DIM_ 2048
#define H_ 16
#define NOPE_ 128
#define ROPE_ 64
#define VD_ 128
#define LORA_ 512
#define QKH_ 192            // NOPE + ROPE
#define KVW_ 576            // LORA + ROPE
#define NQKV_ 3712          // 3072 (q) + 640 (kv padded)
#define KQK_ 192            // per-head qk dim after reassociation
#define SCALE_ 0.07216878364870323f  // 192^-0.5

// ---------------------------------------------------------------------------
// Scratch
// ---------------------------------------------------------------------------
__device__ __nv_bfloat16 d_xhi[(long)S_ * DIM_],      d_xlo[(long)S_ * DIM_];
__device__ __nv_bfloat16 d_wqkvhi[(long)NQKV_ * DIM_],d_wqkvlo[(long)NQKV_ * DIM_];
__device__ __nv_bfloat16 d_wohi[(long)DIM_ * DIM_],   d_wolo[(long)DIM_ * DIM_];
__device__ __nv_bfloat16 d_wkvbhi[(long)H_ * 256 * LORA_], d_wkvblo[(long)H_ * 256 * LORA_];
__device__ __nv_bfloat16 d_qchi[(long)S_ * NQKV_],    d_qclo[(long)S_ * NQKV_];   // q roped in place
__device__ __nv_bfloat16 d_keffhi[(long)S_ * LORA_],  d_kefflo[(long)S_ * LORA_]; // normed kv_c
__device__ __nv_bfloat16 d_kfullhi[(long)H_ * S_ * KQK_];                         // [k_nope | k_pe], hi only
__device__ __nv_bfloat16 d_vThi[(long)H_ * VD_ * S_], d_vTlo[(long)H_ * VD_ * S_];
__device__ __nv_bfloat16 d_attnhi[(long)H_ * S_ * S_],d_attnlo[(long)H_ * S_ * S_];
__device__ __nv_bfloat16 d_o2hi[(long)S_ * DIM_],     d_o2lo[(long)S_ * DIM_];

// ---------------------------------------------------------------------------
// Helpers
// ---------------------------------------------------------------------------
__device__ __forceinline__ uint32_t smem_u32(const void* p) {
    uint32_t a;
    asm("{ .reg .u64 t; cvta.to.shared.u64 t, %1; cvt.u32.u64 %0, t; }"
        : "=r"(a) : "l"(p));
    return a;
}

__device__ __forceinline__ void ldsm_x4(uint32_t* r, uint32_t addr) {
    asm volatile("ldmatrix.sync.aligned.m8n8.x4.shared.b16 {%0,%1,%2,%3}, [%4];"
                 : "=r"(r[0]), "=r"(r[1]), "=r"(r[2]), "=r"(r[3]) : "r"(addr));
}
__device__ __forceinline__ void ldsm_x2(uint32_t* r, uint32_t addr) {
    asm volatile("ldmatrix.sync.aligned.m8n8.x2.shared.b16 {%0,%1}, [%2];"
                 : "=r"(r[0]), "=r"(r[1]) : "r"(addr));
}
__device__ __forceinline__ void mma16816(float* c, const uint32_t* a, const uint32_t* b) {
    asm volatile(
        "mma.sync.aligned.m16n8k16.row.col.f32.bf16.bf16.f32 "
        "{%0,%1,%2,%3}, {%4,%5,%6,%7}, {%8,%9}, {%0,%1,%2,%3};"
        : "+f"(c[0]), "+f"(c[1]), "+f"(c[2]), "+f"(c[3])
        : "r"(a[0]), "r"(a[1]), "r"(a[2]), "r"(a[3]), "r"(b[0]), "r"(b[1]));
}

__device__ __forceinline__ void split2(float v, __nv_bfloat16& h, __nv_bfloat16& l) {
    h = __float2bfloat16(v);
    l = __float2bfloat16(v - __bfloat162float(h));
}
__device__ __forceinline__ float rec2(__nv_bfloat16 h, __nv_bfloat16 l) {
    return __bfloat162float(h) + __bfloat162float(l);
}

// ---------------------------------------------------------------------------
// bf16 split-precision GEMM via mma.sync:
//   C(z) = alpha * A(z)(M,K) @ B(z)(N,K)^T
//   TERMS==3: C ~= Ahi.Bhi + Ahi.Blo + Alo.Bhi  (full split precision)
//   TERMS==1: C ~= Ahi.Bhi                      (plain bf16; lo arrays unread)
// CTA tile 128x128, K chunk 32, cp.async double buffer, 2 CTAs/SM.
// SMEM: 128 rows x 80B pitch -> conflict-free ldmatrix.
// grid = (N/128, M/128, Z); 256 threads (8 warps, warp 64x32).
// causal: 1 = skip tiles with bx > by; 2 = Klim = min(K, row0+128)
// Output: Cf (fp32) and/or Chi / Clo (bf16 hi / lo), each independently optional.
// ---------------------------------------------------------------------------
#define TILE_B 10240            // 128 * 80
#define STAGE_B 40960           // 4 tiles
#define DSMEM_BYTES 81920       // 2 stages

__device__ __forceinline__ void load_tile32(uint32_t dst,
                                            const __nv_bfloat16* __restrict__ src,
                                            int rbase, int ld, int k0, int tid)
{
#pragma unroll
    for (int t = 0; t < 2; t++) {
        int o = tid + t * 256;          // 0..511 : 128 rows x 4 x 16B
        int row = o >> 2, c = o & 3;
        const void* g = (const void*)(src + (long)(rbase + row) * ld + k0 + c * 8);
        asm volatile("cp.async.cg.shared.global [%0], [%1], 16;"
                     :: "r"(dst + row * 80 + c * 16), "l"(g));
    }
}

template <int TERMS>
__global__ void __launch_bounds__(256, 2)
tgemm(const __nv_bfloat16* __restrict__ Ahi, const __nv_bfloat16* __restrict__ Alo,
      long sA, int lda,
      const __nv_bfloat16* __restrict__ Bhi, const __nv_bfloat16* __restrict__ Blo,
      long sB, int ldb,
      float* Cf, __nv_bfloat16* Chi, __nv_bfloat16* Clo,
      long sC, int ldc,
      int K, float alpha, int causal)
{
    const int bx = blockIdx.x, by = blockIdx.y, z = blockIdx.z;
    if (causal == 1 && bx > by) return;
    const int row0 = by * 128, col0 = bx * 128;
    int Klim = (causal == 2) ? min(K, row0 + 128) : K;
    const int nc = Klim >> 5;

    Ahi += (long)z * sA;
    Bhi += (long)z * sB;
    if (TERMS == 3) { Alo += (long)z * sA; Blo += (long)z * sB; }
    if (Cf)  Cf  += (long)z * sC;
    if (Chi) Chi += (long)z * sC;
    if (Clo) Clo += (long)z * sC;

    extern __shared__ char dsm[];
    const uint32_t s0 = smem_u32(dsm);

    const int tid = threadIdx.x;
    const int lane = tid & 31;
    const int wid = tid >> 5;
    const int wm = wid & 1;          // 0..1  (M)
    const int wn = wid >> 1;         // 0..3  (N)

    float acc[4][4][4];
#pragma unroll
    for (int mt = 0; mt < 4; mt++)
#pragma unroll
        for (int nt = 0; nt < 4; nt++)
#pragma unroll
            for (int e = 0; e < 4; e++) acc[mt][nt][e] = 0.f;

    // prologue: fill stage 0
    {
        uint32_t sb = s0;
        load_tile32(sb,              Ahi, row0, lda, 0, tid);
        load_tile32(sb + 2 * TILE_B, Bhi, col0, ldb, 0, tid);
        if (TERMS == 3) {
            load_tile32(sb + TILE_B,     Alo, row0, lda, 0, tid);
            load_tile32(sb + 3 * TILE_B, Blo, col0, ldb, 0, tid);
        }
        asm volatile("cp.async.commit_group;" ::: "memory");
    }

    const uint32_t a_off = (wm * 64 + (lane & 15)) * 80 + ((lane >> 4) << 4);
    const uint32_t b_off = (wn * 32 + (lane & 7)) * 80 + (((lane >> 3) & 1) << 4);

    for (int i = 0; i < nc; i++) {
        if (i + 1 < nc) {
            uint32_t sb = s0 + ((i + 1) & 1) * STAGE_B;
            int k0 = (i + 1) << 5;
            load_tile32(sb,              Ahi, row0, lda, k0, tid);
            load_tile32(sb + 2 * TILE_B, Bhi, col0, ldb, k0, tid);
            if (TERMS == 3) {
                load_tile32(sb + TILE_B,     Alo, row0, lda, k0, tid);
                load_tile32(sb + 3 * TILE_B, Blo, col0, ldb, k0, tid);
            }
            asm volatile("cp.async.commit_group;" ::: "memory");
            asm volatile("cp.async.wait_group 1;" ::: "memory");
        } else {
            asm volatile("cp.async.wait_group 0;" ::: "memory");
        }
        __syncthreads();

        const uint32_t sb = s0 + (i & 1) * STAGE_B;
#pragma unroll
        for (int ks = 0; ks < 2; ks++) {
            const uint32_t kb = ks * 32;
            uint32_t bh[4][2], bl[4][2];
#pragma unroll
            for (int nt = 0; nt < 4; nt++) {
                ldsm_x2(bh[nt], sb + 2 * TILE_B + b_off + nt * (8 * 80) + kb);
                if (TERMS == 3)
                    ldsm_x2(bl[nt], sb + 3 * TILE_B + b_off + nt * (8 * 80) + kb);
            }
#pragma unroll
            for (int mt = 0; mt < 4; mt++) {
                uint32_t ah[4], al[4];
                ldsm_x4(ah, sb + a_off + mt * (16 * 80) + kb);
                if (TERMS == 3)
                    ldsm_x4(al, sb + TILE_B + a_off + mt * (16 * 80) + kb);
#pragma unroll
                for (int nt = 0; nt < 4; nt++) {
                    mma16816(acc[mt][nt], ah, bh[nt]);
                    if (TERMS == 3) {
                        mma16816(acc[mt][nt], ah, bl[nt]);
                        mma16816(acc[mt][nt], al, bh[nt]);
                    }
                }
            }
        }
        __syncthreads();
    }

    // ---------------- epilogue: stage through smem ----------------
    float* stage = (float*)dsm;   // pitch 132 f32: 128*132*4 = 67584 <= 81920
#pragma unroll
    for (int mt = 0; mt < 4; mt++) {
        int r = wm * 64 + mt * 16 + (lane >> 2);
#pragma unroll
        for (int nt = 0; nt < 4; nt++) {
            int c = wn * 32 + nt * 8 + (lane & 3) * 2;
            stage[r * 132 + c]           = acc[mt][nt][0] * alpha;
            stage[r * 132 + c + 1]       = acc[mt][nt][1] * alpha;
            stage[(r + 8) * 132 + c]     = acc[mt][nt][2] * alpha;
            stage[(r + 8) * 132 + c + 1] = acc[mt][nt][3] * alpha;
        }
    }
    __syncthreads();

#pragma unroll
    for (int it = 0; it < 16; it++) {
        int g = tid + it * 256;
        int m = g >> 5, cg = (g & 31) * 4;
        float v0 = stage[m * 132 + cg + 0];
        float v1 = stage[m * 132 + cg + 1];
        float v2 = stage[m * 132 + cg + 2];
        float v3 = stage[m * 132 + cg + 3];
        long off = (long)(row0 + m) * ldc + col0 + cg;
        if (Cf) {
            float4 v = make_float4(v0, v1, v2, v3);
            *(float4*)(Cf + off) = v;
        }
        if (Chi) {
            __nv_bfloat16 h0, h1, h2, h3, l0, l1, l2, l3;
            split2(v0, h0, l0); split2(v1, h1, l1);
            split2(v2, h2, l2); split2(v3, h3, l3);
            *(__nv_bfloat162*)(Chi + off)     = __nv_bfloat162(h0, h1);
            *(__nv_bfloat162*)(Chi + off + 2) = __nv_bfloat162(h2, h3);
            if (Clo) {
                *(__nv_bfloat162*)(Clo + off)     = __nv_bfloat162(l0, l1);
                *(__nv_bfloat162*)(Clo + off + 2) = __nv_bfloat162(l2, l3);
            }
        }
    }
}

// ---------------------------------------------------------------------------
// Pointwise / prep kernels
// ---------------------------------------------------------------------------
__global__ void split_kernel(const float4* __restrict__ in,
                             __nv_bfloat162* __restrict__ hi,
                             __nv_bfloat162* __restrict__ lo, long n4)
{
    long i = (long)blockIdx.x * blockDim.x + threadIdx.x;
    if (i < n4) {
        float4 v = in[i];
        __nv_bfloat16 h0, h1, h2, h3, l0, l1, l2, l3;
        split2(v.x, h0, l0); split2(v.y, h1, l1);
        split2(v.z, h2, l2); split2(v.w, h3, l3);
        hi[2 * i]     = __nv_bfloat162(h0, h1);
        hi[2 * i + 1] = __nv_bfloat162(h2, h3);
        lo[2 * i]     = __nv_bfloat162(l0, l1);
        lo[2 * i + 1] = __nv_bfloat162(l2, l3);
    }
}

// concat wq (3072x2048) + wkv_a (576x2048, zero-padded to 640) -> 3712x2048
__global__ void split_concat_wqkv(const float4* __restrict__ wq,
                                  const float4* __restrict__ wkva,
                                  __nv_bfloat162* __restrict__ hi,
                                  __nv_bfloat162* __restrict__ lo)
{
    long i = (long)blockIdx.x * blockDim.x + threadIdx.x;  // float4 index
    long n4 = (long)NQKV_ * DIM_ / 4;
    if (i < n4) {
        long r = i / (DIM_ / 4);
        float4 v;
        if (r < 3072)             v = wq[i];
        else if (r < 3072 + KVW_) v = wkva[i - (long)3072 * (DIM_ / 4)];
        else                      v = make_float4(0.f, 0.f, 0.f, 0.f);
        __nv_bfloat16 h0, h1, h2, h3, l0, l1, l2, l3;
        split2(v.x, h0, l0); split2(v.y, h1, l1);
        split2(v.z, h2, l2); split2(v.w, h3, l3);
        hi[2 * i]     = __nv_bfloat162(h0, h1);
        hi[2 * i + 1] = __nv_bfloat162(h2, h3);
        lo[2 * i]     = __nv_bfloat162(l0, l1);
        lo[2 * i + 1] = __nv_bfloat162(l2, l3);
    }
}

// rmsnorm(kv_c) -> keff hi/lo ; rope(k_pe) -> kfull cols 128..191 (all heads, hi only);
// rope(q_pe) in place in qchi/qclo. qc layout: [q(3072) | kv(640)] per row.
__global__ void prep_kernel(__nv_bfloat16* __restrict__ qchi,
                            __nv_bfloat16* __restrict__ qclo,
                            const float* __restrict__ cosb,
                            const float* __restrict__ sinb,
                            const float* __restrict__ knw,
                            __nv_bfloat16* __restrict__ keffhi,
                            __nv_bfloat16* __restrict__ kefflo,
                            __nv_bfloat16* __restrict__ kfullhi)
{
    const int s = blockIdx.x;
    const int tid = threadIdx.x;
    __nv_bfloat16* kvhi = qchi + (long)s * NQKV_ + 3072;
    __nv_bfloat16* kvlo = qclo + (long)s * NQKV_ + 3072;
    __shared__ float red[256];

    // rmsnorm over kv_c (512)
    float ss = 0.f;
    for (int c = tid; c < LORA_; c += 256) {
        float v = rec2(kvhi[c], kvlo[c]);
        ss += v * v;
    }
    red[tid] = ss;
    __syncthreads();
    for (int w = 128; w > 0; w >>= 1) {
        if (tid < w) red[tid] += red[tid + w];
        __syncthreads();
    }
    float r = rsqrtf(red[0] / (float)LORA_ + 1e-6f);
    for (int c = tid; c < LORA_; c += 256) {
        float v = rec2(kvhi[c], kvlo[c]);
        __nv_bfloat16 h, l;
        split2(v * r * knw[c], h, l);
        keffhi[(long)s * LORA_ + c] = h;
        kefflo[(long)s * LORA_ + c] = l;
    }

    const float* cs = cosb + s * (ROPE_ / 2);
    const float* sn = sinb + s * (ROPE_ / 2);

    // rope k_pe -> kfull[h][s][128+...] for all 16 heads (hi only)
    for (int idx = tid; idx < H_ * 32; idx += 256) {
        int h = idx >> 5, i = idx & 31;
        float x0 = rec2(kvhi[LORA_ + 2 * i], kvlo[LORA_ + 2 * i]);
        float x1 = rec2(kvhi[LORA_ + 2 * i + 1], kvlo[LORA_ + 2 * i + 1]);
        float y0 = x0 * cs[i] - x1 * sn[i];
        float y1 = x0 * sn[i] + x1 * cs[i];
        long base = ((long)h * S_ + s) * KQK_ + NOPE_;
        kfullhi[base + 2 * i]     = __float2bfloat16(y0);
        kfullhi[base + 2 * i + 1] = __float2bfloat16(y1);
    }

    // rope q_pe in place (per head cols h*192+128 .. +191)
    for (int idx = tid; idx < H_ * 32; idx += 256) {
        int h = idx >> 5, i = idx & 31;
        long base = (long)s * NQKV_ + h * QKH_ + NOPE_;
        float x0 = rec2(qchi[base + 2 * i], qclo[base + 2 * i]);
        float x1 = rec2(qchi[base + 2 * i + 1], qclo[base + 2 * i + 1]);
        float y0 = x0 * cs[i] - x1 * sn[i];
        float y1 = x0 * sn[i] + x1 * cs[i];
        __nv_bfloat16 hh, ll;
        split2(y0, hh, ll);
        qchi[base + 2 * i] = hh; qclo[base + 2 * i] = ll;
        split2(y1, hh, ll);
        qchi[base + 2 * i + 1] = hh; qclo[base + 2 * i + 1] = ll;
    }
}

// causal softmax: read scores (bf16 hi only, in attnhi), write attn hi/lo.
// Thread t owns 8 contiguous cols; uint4 reads, bf162 stores.
// Zero-fill only to the 128-aligned diagonal tile boundary.
__global__ void softmax_kernel(__nv_bfloat16* __restrict__ attnhi,
                               __nv_bfloat16* __restrict__ attnlo)
{
    const int s = blockIdx.x, h = blockIdx.y;
    __nv_bfloat16* ohi = attnhi + ((long)h * S_ + s) * S_;
    __nv_bfloat16* olo = attnlo + ((long)h * S_ + s) * S_;
    const int n = s + 1;
    const int nz = ((s >> 7) + 1) << 7;   // round up to 128
    const int tid = threadIdx.x;
    const int lane = tid & 31, wid = tid >> 5;
    const int c0 = tid * 8;
    __shared__ float wred[8];

    float vals[8];
    float m = -1e30f;
    if (c0 < nz) {
        uint4 hv = *(const uint4*)(ohi + c0);
        const __nv_bfloat162* hp = (const __nv_bfloat162*)&hv;
#pragma unroll
        for (int j = 0; j < 4; j++) {
            float2 hf = __bfloat1622float2(hp[j]);
            vals[2 * j]     = hf.x;
            vals[2 * j + 1] = hf.y;
        }
#pragma unroll
        for (int j = 0; j < 8; j++)
            if (c0 + j < n) m = fmaxf(m, vals[j]);
    }
#pragma unroll
    for (int o = 16; o > 0; o >>= 1)
        m = fmaxf(m, __shfl_xor_sync(0xffffffffu, m, o));
    if (lane == 0) wred[wid] = m;
    __syncthreads();
    m = -1e30f;
#pragma unroll
    for (int w = 0; w < 8; w++) m = fmaxf(m, wred[w]);
    __syncthreads();

    float sum = 0.f;
    if (c0 < nz) {
#pragma unroll
        for (int j = 0; j < 8; j++) {
            float e = (c0 + j < n) ? __expf(vals[j] - m) : 0.f;
            vals[j] = e;
            sum += e;
        }
    }
#pragma unroll
    for (int o = 16; o > 0; o >>= 1)
        sum += __shfl_xor_sync(0xffffffffu, sum, o);
    if (lane == 0) wred[wid] = sum;
    __syncthreads();
    sum = 0.f;
#pragma unroll
    for (int w = 0; w < 8; w++) sum += wred[w];
    float inv = 1.0f / sum;

    if (c0 < nz) {
        __nv_bfloat162 hv[4], lv[4];
#pragma unroll
        for (int j = 0; j < 4; j++) {
            __nv_bfloat16 h0, h1, l0, l1;
            split2(vals[2 * j] * inv, h0, l0);
            split2(vals[2 * j + 1] * inv, h1, l1);
            hv[j] = __nv_bfloat162(h0, h1);
            lv[j] = __nv_bfloat162(l0, l1);
        }
        *(uint4*)(ohi + c0) = *(uint4*)hv;
        *(uint4*)(olo + c0) = *(uint4*)lv;
    }
}

// ---------------------------------------------------------------------------
// Launch
// ---------------------------------------------------------------------------
extern "C" void kernel_launch(void* const* d_in, const int* in_sizes, int n_in,
                              void* d_out, int out_size)
{
    const float* x     = (const float*)d_in[0];
    const float* cosb  = (const float*)d_in[1];
    const float* sinb  = (const float*)d_in[2];
    const float* wq    = (const float*)d_in[3];
    const float* wkv_a = (const float*)d_in[4];
    const float* knw   = (const float*)d_in[5];
    const float* wkv_b = (const float*)d_in[6];
    const float* wo    = (const float*)d_in[7];
    float* out = (float*)d_out;

    cudaFuncSetAttribute(tgemm<3>, cudaFuncAttributeMaxDynamicSharedMemorySize,
                         DSMEM_BYTES);
    cudaFuncSetAttribute(tgemm<1>, cudaFuncAttributeMaxDynamicSharedMemorySize,
                         DSMEM_BYTES);

    __nv_bfloat16 *xhi,*xlo,*wqkvhi,*wqkvlo,*wohi,*wolo,*wkvbhi,*wkvblo;
    __nv_bfloat16 *qchi,*qclo,*keffhi,*kefflo,*kfullhi;
    __nv_bfloat16 *vThi,*vTlo,*attnhi,*attnlo,*o2hi,*o2lo;
    cudaGetSymbolAddress((void**)&xhi, d_xhi);       cudaGetSymbolAddress((void**)&xlo, d_xlo);
    cudaGetSymbolAddress((void**)&wqkvhi, d_wqkvhi); cudaGetSymbolAddress((void**)&wqkvlo, d_wqkvlo);
    cudaGetSymbolAddress((void**)&wohi, d_wohi);     cudaGetSymbolAddress((void**)&wolo, d_wolo);
    cudaGetSymbolAddress((void**)&wkvbhi, d_wkvbhi); cudaGetSymbolAddress((void**)&wkvblo, d_wkvblo);
    cudaGetSymbolAddress((void**)&qchi, d_qchi);     cudaGetSymbolAddress((void**)&qclo, d_qclo);
    cudaGetSymbolAddress((void**)&keffhi, d_keffhi); cudaGetSymbolAddress((void**)&kefflo, d_kefflo);
    cudaGetSymbolAddress((void**)&kfullhi, d_kfullhi);
    cudaGetSymbolAddress((void**)&vThi, d_vThi);     cudaGetSymbolAddress((void**)&vTlo, d_vTlo);
    cudaGetSymbolAddress((void**)&attnhi, d_attnhi); cudaGetSymbolAddress((void**)&attnlo, d_attnlo);
    cudaGetSymbolAddress((void**)&o2hi, d_o2hi);     cudaGetSymbolAddress((void**)&o2lo, d_o2lo);

    // -------- operand splits --------
    {
        long n4;
        n4 = (long)S_ * DIM_ / 4;
        split_kernel<<<(n4 + 255) / 256, 256>>>(
            (const float4*)x, (__nv_bfloat162*)xhi, (__nv_bfloat162*)xlo, n4);
        n4 = (long)NQKV_ * DIM_ / 4;
        split_concat_wqkv<<<(n4 + 255) / 256, 256>>>(
            (const float4*)wq, (const float4*)wkv_a,
            (__nv_bfloat162*)wqkvhi, (__nv_bfloat162*)wqkvlo);
        n4 = (long)DIM_ * DIM_ / 4;
        split_kernel<<<(n4 + 255) / 256, 256>>>(
            (const float4*)wo, (__nv_bfloat162*)wohi, (__nv_bfloat162*)wolo, n4);
        n4 = (long)H_ * 256 * LORA_ / 4;
        split_kernel<<<(n4 + 255) / 256, 256>>>(
            (const float4*)wkv_b, (__nv_bfloat162*)wkvbhi, (__nv_bfloat162*)wkvblo, n4);
    }

    // 1. [q | kv] = x @ [wq | wkv_a]^T  (2048 x 3712), hi/lo (3-term)
    tgemm<3><<<dim3(NQKV_ / 128, 16, 1), 256, DSMEM_BYTES>>>(
        xhi, xlo, 0, DIM_, wqkvhi, wqkvlo, 0, DIM_,
        nullptr, qchi, qclo, 0, NQKV_, DIM_, 1.f, 0);

    // 2. prep: rmsnorm + rope (q in place, k_pe into kfull hi, keff out)
    prep_kernel<<<S_, 256>>>(qchi, qclo, cosb, sinb, knw,
                             keffhi, kefflo, kfullhi);

    // 3. k_nope[h] = keff @ w_uk[h]^T -> kfull[h] cols 0..127 (1-term, hi out)
    tgemm<1><<<dim3(1, 16, H_), 256, DSMEM_BYTES>>>(
        keffhi, nullptr, 0, LORA_,
        wkvbhi, nullptr, (long)256 * LORA_, LORA_,
        nullptr, kfullhi, nullptr, (long)S_ * KQK_, KQK_, LORA_, 1.f, 0);

    // 4. vT[h] = w_uv[h] @ keff^T  (M=128 d, N=2048 t, K=512) (3-term)
    tgemm<3><<<dim3(16, 1, H_), 256, DSMEM_BYTES>>>(
        wkvbhi + (long)NOPE_ * LORA_, wkvblo + (long)NOPE_ * LORA_,
        (long)256 * LORA_, LORA_,
        keffhi, kefflo, 0, LORA_,
        nullptr, vThi, vTlo, (long)VD_ * S_, S_, LORA_, 1.f, 0);

    // 5. scores[h] = SCALE * q[h](K=192) @ kfull[h]^T (1-term, hi out, causal skip)
    tgemm<1><<<dim3(16, 16, H_), 256, DSMEM_BYTES>>>(
        qchi, nullptr, (long)QKH_, NQKV_,
        kfullhi, nullptr, (long)S_ * KQK_, KQK_,
        nullptr, attnhi, nullptr, (long)S_ * S_, S_, KQK_, SCALE_, 1);

    // 6. softmax: scores hi -> attn hi/lo
    softmax_kernel<<<dim3(S_, H_), 256>>>(attnhi, attnlo);

    // 7. o2[:, h*128:+128] = attn[h] @ vT[h]^T  (3-term, K diag-limited)
    tgemm<3><<<dim3(1, 16, H_), 256, DSMEM_BYTES>>>(
        attnhi, attnlo, (long)S_ * S_, S_,
        vThi, vTlo, (long)VD_ * S_, S_,
        nullptr, o2hi, o2lo, (long)VD_, DIM_, S_, 1.f, 2);

    // 8. out = o2 @ wo^T  (3-term)
    tgemm<3><<<dim3(16, 16, 1), 256, DSMEM_BYTES>>>(
        o2hi, o2lo, 0, DIM_, wohi, wolo, 0, DIM_,
        out, nullptr, nullptr, 0, DIM_, DIM_, 1.f, 0);
}

// round 11
// speedup vs baseline: 1.7281x; 1.0341x over previous
#include <cuda_runtime.h>
#include <cuda_bf16.h>
#include <cstdint>

// ---------------------------------------------------------------------------
// Problem constants
// ---------------------------------------------------------------------------
#define S_ 2048
#define DIM_ 2048
#define H_ 16
#define NOPE_ 128
#define ROPE_ 64
#define VD_ 128
#define LORA_ 512
#define QKH_ 192            // NOPE + ROPE
#define KVW_ 576            // LORA + ROPE
#define NQKV_ 3712          // 3072 (q) + 640 (kv padded)
#define KQK_ 192            // per-head qk dim after reassociation
#define SCALE_ 0.07216878364870323f  // 192^-0.5

// ---------------------------------------------------------------------------
// Scratch
// ---------------------------------------------------------------------------
__device__ __nv_bfloat16 d_xhi[(long)S_ * DIM_],      d_xlo[(long)S_ * DIM_];
__device__ __nv_bfloat16 d_wqkvhi[(long)NQKV_ * DIM_],d_wqkvlo[(long)NQKV_ * DIM_];
__device__ __nv_bfloat16 d_wohi[(long)DIM_ * DIM_],   d_wolo[(long)DIM_ * DIM_];
__device__ __nv_bfloat16 d_wkvbhi[(long)H_ * 256 * LORA_], d_wkvblo[(long)H_ * 256 * LORA_];
__device__ __nv_bfloat16 d_qchi[(long)S_ * NQKV_],    d_qclo[(long)S_ * NQKV_];   // q roped in place
__device__ __nv_bfloat16 d_keffhi[(long)S_ * LORA_],  d_kefflo[(long)S_ * LORA_]; // normed kv_c
__device__ __nv_bfloat16 d_kfullhi[(long)H_ * S_ * KQK_];                         // [k_nope | k_pe], hi only
__device__ __nv_bfloat16 d_vThi[(long)H_ * VD_ * S_], d_vTlo[(long)H_ * VD_ * S_];
__device__ __nv_bfloat16 d_attnhi[(long)H_ * S_ * S_],d_attnlo[(long)H_ * S_ * S_];
__device__ float         d_o2p[2][(long)S_ * DIM_];   // split-K fp32 partials
__device__ __nv_bfloat16 d_o2hi[(long)S_ * DIM_],     d_o2lo[(long)S_ * DIM_];

// ---------------------------------------------------------------------------
// Helpers
// ---------------------------------------------------------------------------
__device__ __forceinline__ uint32_t smem_u32(const void* p) {
    uint32_t a;
    asm("{ .reg .u64 t; cvta.to.shared.u64 t, %1; cvt.u32.u64 %0, t; }"
        : "=r"(a) : "l"(p));
    return a;
}

__device__ __forceinline__ void ldsm_x4(uint32_t* r, uint32_t addr) {
    asm volatile("ldmatrix.sync.aligned.m8n8.x4.shared.b16 {%0,%1,%2,%3}, [%4];"
                 : "=r"(r[0]), "=r"(r[1]), "=r"(r[2]), "=r"(r[3]) : "r"(addr));
}
__device__ __forceinline__ void ldsm_x2(uint32_t* r, uint32_t addr) {
    asm volatile("ldmatrix.sync.aligned.m8n8.x2.shared.b16 {%0,%1}, [%2];"
                 : "=r"(r[0]), "=r"(r[1]) : "r"(addr));
}
__device__ __forceinline__ void mma16816(float* c, const uint32_t* a, const uint32_t* b) {
    asm volatile(
        "mma.sync.aligned.m16n8k16.row.col.f32.bf16.bf16.f32 "
        "{%0,%1,%2,%3}, {%4,%5,%6,%7}, {%8,%9}, {%0,%1,%2,%3};"
        : "+f"(c[0]), "+f"(c[1]), "+f"(c[2]), "+f"(c[3])
        : "r"(a[0]), "r"(a[1]), "r"(a[2]), "r"(a[3]), "r"(b[0]), "r"(b[1]));
}

__device__ __forceinline__ void split2(float v, __nv_bfloat16& h, __nv_bfloat16& l) {
    h = __float2bfloat16(v);
    l = __float2bfloat16(v - __bfloat162float(h));
}
__device__ __forceinline__ float rec2(__nv_bfloat16 h, __nv_bfloat16 l) {
    return __bfloat162float(h) + __bfloat162float(l);
}

// ---------------------------------------------------------------------------
// bf16 split-precision GEMM via mma.sync:
//   C(z) = alpha * A(z)(M,K) @ B(z)(N,K)^T
//   TERMS==3: C ~= Ahi.Bhi + Ahi.Blo + Alo.Bhi ; TERMS==1: C ~= Ahi.Bhi
// CTA tile 128x128, K chunk 32, cp.async double buffer, 2 CTAs/SM.
// grid = (N/128, M/128, Z) normally.
// causal: 1 = skip tiles with bx > by; 2 = Klim = min(K, row0+128)
// ksplit > 0: split-K mode (requires N == 128): bx indexes the K-split,
//   col0 = 0, this CTA covers k in [bx*ksplit, min(Klim, (bx+1)*ksplit)),
//   and Cf is offset by bx * sSplit (separate partial buffers).
// ---------------------------------------------------------------------------
#define TILE_B 10240            // 128 * 80
#define STAGE_B 40960           // 4 tiles
#define DSMEM_BYTES 81920       // 2 stages

__device__ __forceinline__ void load_tile32(uint32_t dst,
                                            const __nv_bfloat16* __restrict__ src,
                                            int rbase, int ld, int k0, int tid)
{
#pragma unroll
    for (int t = 0; t < 2; t++) {
        int o = tid + t * 256;          // 0..511 : 128 rows x 4 x 16B
        int row = o >> 2, c = o & 3;
        const void* g = (const void*)(src + (long)(rbase + row) * ld + k0 + c * 8);
        asm volatile("cp.async.cg.shared.global [%0], [%1], 16;"
                     :: "r"(dst + row * 80 + c * 16), "l"(g));
    }
}

template <int TERMS>
__global__ void __launch_bounds__(256, 2)
tgemm(const __nv_bfloat16* __restrict__ Ahi, const __nv_bfloat16* __restrict__ Alo,
      long sA, int lda,
      const __nv_bfloat16* __restrict__ Bhi, const __nv_bfloat16* __restrict__ Blo,
      long sB, int ldb,
      float* Cf, __nv_bfloat16* Chi, __nv_bfloat16* Clo,
      long sC, int ldc,
      int K, float alpha, int causal,
      int ksplit, long sSplit)
{
    const int bx = blockIdx.x, by = blockIdx.y, z = blockIdx.z;
    if (causal == 1 && bx > by) return;
    const int row0 = by * 128;
    int col0 = bx * 128;
    int Klim = (causal == 2) ? min(K, row0 + 128) : K;
    int kstart = 0, kend = Klim;
    if (ksplit > 0) {
        col0 = 0;
        kstart = bx * ksplit;
        kend = min(Klim, kstart + ksplit);
        if (kstart >= kend) return;
        if (Cf) Cf += (long)bx * sSplit;
    }
    const int c0 = kstart >> 5, c1 = kend >> 5;

    Ahi += (long)z * sA;
    Bhi += (long)z * sB;
    if (TERMS == 3) { Alo += (long)z * sA; Blo += (long)z * sB; }
    if (Cf)  Cf  += (long)z * sC;
    if (Chi) Chi += (long)z * sC;
    if (Clo) Clo += (long)z * sC;

    extern __shared__ char dsm[];
    const uint32_t s0 = smem_u32(dsm);

    const int tid = threadIdx.x;
    const int lane = tid & 31;
    const int wid = tid >> 5;
    const int wm = wid & 1;          // 0..1  (M)
    const int wn = wid >> 1;         // 0..3  (N)

    float acc[4][4][4];
#pragma unroll
    for (int mt = 0; mt < 4; mt++)
#pragma unroll
        for (int nt = 0; nt < 4; nt++)
#pragma unroll
            for (int e = 0; e < 4; e++) acc[mt][nt][e] = 0.f;

    // prologue: fill stage (c0 & 1)
    {
        uint32_t sb = s0 + (c0 & 1) * STAGE_B;
        int k0 = c0 << 5;
        load_tile32(sb,              Ahi, row0, lda, k0, tid);
        load_tile32(sb + 2 * TILE_B, Bhi, col0, ldb, k0, tid);
        if (TERMS == 3) {
            load_tile32(sb + TILE_B,     Alo, row0, lda, k0, tid);
            load_tile32(sb + 3 * TILE_B, Blo, col0, ldb, k0, tid);
        }
        asm volatile("cp.async.commit_group;" ::: "memory");
    }

    const uint32_t a_off = (wm * 64 + (lane & 15)) * 80 + ((lane >> 4) << 4);
    const uint32_t b_off = (wn * 32 + (lane & 7)) * 80 + (((lane >> 3) & 1) << 4);

    for (int i = c0; i < c1; i++) {
        if (i + 1 < c1) {
            uint32_t sb = s0 + ((i + 1) & 1) * STAGE_B;
            int k0 = (i + 1) << 5;
            load_tile32(sb,              Ahi, row0, lda, k0, tid);
            load_tile32(sb + 2 * TILE_B, Bhi, col0, ldb, k0, tid);
            if (TERMS == 3) {
                load_tile32(sb + TILE_B,     Alo, row0, lda, k0, tid);
                load_tile32(sb + 3 * TILE_B, Blo, col0, ldb, k0, tid);
            }
            asm volatile("cp.async.commit_group;" ::: "memory");
            asm volatile("cp.async.wait_group 1;" ::: "memory");
        } else {
            asm volatile("cp.async.wait_group 0;" ::: "memory");
        }
        __syncthreads();

        const uint32_t sb = s0 + (i & 1) * STAGE_B;
#pragma unroll
        for (int ks = 0; ks < 2; ks++) {
            const uint32_t kb = ks * 32;
            uint32_t bh[4][2], bl[4][2];
#pragma unroll
            for (int nt = 0; nt < 4; nt++) {
                ldsm_x2(bh[nt], sb + 2 * TILE_B + b_off + nt * (8 * 80) + kb);
                if (TERMS == 3)
                    ldsm_x2(bl[nt], sb + 3 * TILE_B + b_off + nt * (8 * 80) + kb);
            }
#pragma unroll
            for (int mt = 0; mt < 4; mt++) {
                uint32_t ah[4], al[4];
                ldsm_x4(ah, sb + a_off + mt * (16 * 80) + kb);
                if (TERMS == 3)
                    ldsm_x4(al, sb + TILE_B + a_off + mt * (16 * 80) + kb);
#pragma unroll
                for (int nt = 0; nt < 4; nt++) {
                    mma16816(acc[mt][nt], ah, bh[nt]);
                    if (TERMS == 3) {
                        mma16816(acc[mt][nt], ah, bl[nt]);
                        mma16816(acc[mt][nt], al, bh[nt]);
                    }
                }
            }
        }
        __syncthreads();
    }

    // ---------------- epilogue: stage through smem ----------------
    float* stage = (float*)dsm;   // pitch 132 f32: 128*132*4 = 67584 <= 81920
#pragma unroll
    for (int mt = 0; mt < 4; mt++) {
        int r = wm * 64 + mt * 16 + (lane >> 2);
#pragma unroll
        for (int nt = 0; nt < 4; nt++) {
            int c = wn * 32 + nt * 8 + (lane & 3) * 2;
            stage[r * 132 + c]           = acc[mt][nt][0] * alpha;
            stage[r * 132 + c + 1]       = acc[mt][nt][1] * alpha;
            stage[(r + 8) * 132 + c]     = acc[mt][nt][2] * alpha;
            stage[(r + 8) * 132 + c + 1] = acc[mt][nt][3] * alpha;
        }
    }
    __syncthreads();

#pragma unroll
    for (int it = 0; it < 16; it++) {
        int g = tid + it * 256;
        int m = g >> 5, cg = (g & 31) * 4;
        float v0 = stage[m * 132 + cg + 0];
        float v1 = stage[m * 132 + cg + 1];
        float v2 = stage[m * 132 + cg + 2];
        float v3 = stage[m * 132 + cg + 3];
        long off = (long)(row0 + m) * ldc + col0 + cg;
        if (Cf) {
            float4 v = make_float4(v0, v1, v2, v3);
            *(float4*)(Cf + off) = v;
        }
        if (Chi) {
            __nv_bfloat16 h0, h1, h2, h3, l0, l1, l2, l3;
            split2(v0, h0, l0); split2(v1, h1, l1);
            split2(v2, h2, l2); split2(v3, h3, l3);
            *(__nv_bfloat162*)(Chi + off)     = __nv_bfloat162(h0, h1);
            *(__nv_bfloat162*)(Chi + off + 2) = __nv_bfloat162(h2, h3);
            if (Clo) {
                *(__nv_bfloat162*)(Clo + off)     = __nv_bfloat162(l0, l1);
                *(__nv_bfloat162*)(Clo + off + 2) = __nv_bfloat162(l2, l3);
            }
        }
    }
}

// ---------------------------------------------------------------------------
// Pointwise / prep kernels
// ---------------------------------------------------------------------------
__global__ void split_kernel(const float4* __restrict__ in,
                             __nv_bfloat162* __restrict__ hi,
                             __nv_bfloat162* __restrict__ lo, long n4)
{
    long i = (long)blockIdx.x * blockDim.x + threadIdx.x;
    if (i < n4) {
        float4 v = in[i];
        __nv_bfloat16 h0, h1, h2, h3, l0, l1, l2, l3;
        split2(v.x, h0, l0); split2(v.y, h1, l1);
        split2(v.z, h2, l2); split2(v.w, h3, l3);
        hi[2 * i]     = __nv_bfloat162(h0, h1);
        hi[2 * i + 1] = __nv_bfloat162(h2, h3);
        lo[2 * i]     = __nv_bfloat162(l0, l1);
        lo[2 * i + 1] = __nv_bfloat162(l2, l3);
    }
}

// concat wq (3072x2048) + wkv_a (576x2048, zero-padded to 640) -> 3712x2048
__global__ void split_concat_wqkv(const float4* __restrict__ wq,
                                  const float4* __restrict__ wkva,
                                  __nv_bfloat162* __restrict__ hi,
                                  __nv_bfloat162* __restrict__ lo)
{
    long i = (long)blockIdx.x * blockDim.x + threadIdx.x;  // float4 index
    long n4 = (long)NQKV_ * DIM_ / 4;
    if (i < n4) {
        long r = i / (DIM_ / 4);
        float4 v;
        if (r < 3072)             v = wq[i];
        else if (r < 3072 + KVW_) v = wkva[i - (long)3072 * (DIM_ / 4)];
        else                      v = make_float4(0.f, 0.f, 0.f, 0.f);
        __nv_bfloat16 h0, h1, h2, h3, l0, l1, l2, l3;
        split2(v.x, h0, l0); split2(v.y, h1, l1);
        split2(v.z, h2, l2); split2(v.w, h3, l3);
        hi[2 * i]     = __nv_bfloat162(h0, h1);
        hi[2 * i + 1] = __nv_bfloat162(h2, h3);
        lo[2 * i]     = __nv_bfloat162(l0, l1);
        lo[2 * i + 1] = __nv_bfloat162(l2, l3);
    }
}

// o2 = o2a + (row >= 1024 ? o2b : 0), split to hi/lo. 4 floats/thread.
__global__ void o2add_kernel(const float4* __restrict__ a,
                             const float4* __restrict__ b,
                             __nv_bfloat162* __restrict__ hi,
                             __nv_bfloat162* __restrict__ lo)
{
    long i = (long)blockIdx.x * blockDim.x + threadIdx.x;  // float4 index
    long n4 = (long)S_ * DIM_ / 4;
    if (i < n4) {
        long row = i / (DIM_ / 4);
        float4 v = a[i];
        if (row >= 1024) {
            float4 w = b[i];
            v.x += w.x; v.y += w.y; v.z += w.z; v.w += w.w;
        }
        __nv_bfloat16 h0, h1, h2, h3, l0, l1, l2, l3;
        split2(v.x, h0, l0); split2(v.y, h1, l1);
        split2(v.z, h2, l2); split2(v.w, h3, l3);
        hi[2 * i]     = __nv_bfloat162(h0, h1);
        hi[2 * i + 1] = __nv_bfloat162(h2, h3);
        lo[2 * i]     = __nv_bfloat162(l0, l1);
        lo[2 * i + 1] = __nv_bfloat162(l2, l3);
    }
}

// rmsnorm(kv_c) -> keff hi/lo ; rope(k_pe) -> kfull cols 128..191 (all heads, hi only);
// rope(q_pe) in place in qchi/qclo. qc layout: [q(3072) | kv(640)] per row.
__global__ void prep_kernel(__nv_bfloat16* __restrict__ qchi,
                            __nv_bfloat16* __restrict__ qclo,
                            const float* __restrict__ cosb,
                            const float* __restrict__ sinb,
                            const float* __restrict__ knw,
                            __nv_bfloat16* __restrict__ keffhi,
                            __nv_bfloat16* __restrict__ kefflo,
                            __nv_bfloat16* __restrict__ kfullhi)
{
    const int s = blockIdx.x;
    const int tid = threadIdx.x;
    __nv_bfloat16* kvhi = qchi + (long)s * NQKV_ + 3072;
    __nv_bfloat16* kvlo = qclo + (long)s * NQKV_ + 3072;
    __shared__ float red[256];

    float ss = 0.f;
    for (int c = tid; c < LORA_; c += 256) {
        float v = rec2(kvhi[c], kvlo[c]);
        ss += v * v;
    }
    red[tid] = ss;
    __syncthreads();
    for (int w = 128; w > 0; w >>= 1) {
        if (tid < w) red[tid] += red[tid + w];
        __syncthreads();
    }
    float r = rsqrtf(red[0] / (float)LORA_ + 1e-6f);
    for (int c = tid; c < LORA_; c += 256) {
        float v = rec2(kvhi[c], kvlo[c]);
        __nv_bfloat16 h, l;
        split2(v * r * knw[c], h, l);
        keffhi[(long)s * LORA_ + c] = h;
        kefflo[(long)s * LORA_ + c] = l;
    }

    const float* cs = cosb + s * (ROPE_ / 2);
    const float* sn = sinb + s * (ROPE_ / 2);

    for (int idx = tid; idx < H_ * 32; idx += 256) {
        int h = idx >> 5, i = idx & 31;
        float x0 = rec2(kvhi[LORA_ + 2 * i], kvlo[LORA_ + 2 * i]);
        float x1 = rec2(kvhi[LORA_ + 2 * i + 1], kvlo[LORA_ + 2 * i + 1]);
        float y0 = x0 * cs[i] - x1 * sn[i];
        float y1 = x0 * sn[i] + x1 * cs[i];
        long base = ((long)h * S_ + s) * KQK_ + NOPE_;
        kfullhi[base + 2 * i]     = __float2bfloat16(y0);
        kfullhi[base + 2 * i + 1] = __float2bfloat16(y1);
    }

    for (int idx = tid; idx < H_ * 32; idx += 256) {
        int h = idx >> 5, i = idx & 31;
        long base = (long)s * NQKV_ + h * QKH_ + NOPE_;
        float x0 = rec2(qchi[base + 2 * i], qclo[base + 2 * i]);
        float x1 = rec2(qchi[base + 2 * i + 1], qclo[base + 2 * i + 1]);
        float y0 = x0 * cs[i] - x1 * sn[i];
        float y1 = x0 * sn[i] + x1 * cs[i];
        __nv_bfloat16 hh, ll;
        split2(y0, hh, ll);
        qchi[base + 2 * i] = hh; qclo[base + 2 * i] = ll;
        split2(y1, hh, ll);
        qchi[base + 2 * i + 1] = hh; qclo[base + 2 * i + 1] = ll;
    }
}

// causal softmax: read scores (bf16 hi only, in attnhi), write attn hi/lo.
__global__ void softmax_kernel(__nv_bfloat16* __restrict__ attnhi,
                               __nv_bfloat16* __restrict__ attnlo)
{
    const int s = blockIdx.x, h = blockIdx.y;
    __nv_bfloat16* ohi = attnhi + ((long)h * S_ + s) * S_;
    __nv_bfloat16* olo = attnlo + ((long)h * S_ + s) * S_;
    const int n = s + 1;
    const int nz = ((s >> 7) + 1) << 7;   // round up to 128
    const int tid = threadIdx.x;
    const int lane = tid & 31, wid = tid >> 5;
    const int c0 = tid * 8;
    __shared__ float wred[8];

    float vals[8];
    float m = -1e30f;
    if (c0 < nz) {
        uint4 hv = *(const uint4*)(ohi + c0);
        const __nv_bfloat162* hp = (const __nv_bfloat162*)&hv;
#pragma unroll
        for (int j = 0; j < 4; j++) {
            float2 hf = __bfloat1622float2(hp[j]);
            vals[2 * j]     = hf.x;
            vals[2 * j + 1] = hf.y;
        }
#pragma unroll
        for (int j = 0; j < 8; j++)
            if (c0 + j < n) m = fmaxf(m, vals[j]);
    }
#pragma unroll
    for (int o = 16; o > 0; o >>= 1)
        m = fmaxf(m, __shfl_xor_sync(0xffffffffu, m, o));
    if (lane == 0) wred[wid] = m;
    __syncthreads();
    m = -1e30f;
#pragma unroll
    for (int w = 0; w < 8; w++) m = fmaxf(m, wred[w]);
    __syncthreads();

    float sum = 0.f;
    if (c0 < nz) {
#pragma unroll
        for (int j = 0; j < 8; j++) {
            float e = (c0 + j < n) ? __expf(vals[j] - m) : 0.f;
            vals[j] = e;
            sum += e;
        }
    }
#pragma unroll
    for (int o = 16; o > 0; o >>= 1)
        sum += __shfl_xor_sync(0xffffffffu, sum, o);
    if (lane == 0) wred[wid] = sum;
    __syncthreads();
    sum = 0.f;
#pragma unroll
    for (int w = 0; w < 8; w++) sum += wred[w];
    float inv = 1.0f / sum;

    if (c0 < nz) {
        __nv_bfloat162 hv[4], lv[4];
#pragma unroll
        for (int j = 0; j < 4; j++) {
            __nv_bfloat16 h0, h1, l0, l1;
            split2(vals[2 * j] * inv, h0, l0);
            split2(vals[2 * j + 1] * inv, h1, l1);
            hv[j] = __nv_bfloat162(h0, h1);
            lv[j] = __nv_bfloat162(l0, l1);
        }
        *(uint4*)(ohi + c0) = *(uint4*)hv;
        *(uint4*)(olo + c0) = *(uint4*)lv;
    }
}

// ---------------------------------------------------------------------------
// Launch
// ---------------------------------------------------------------------------
extern "C" void kernel_launch(void* const* d_in, const int* in_sizes, int n_in,
                              void* d_out, int out_size)
{
    const float* x     = (const float*)d_in[0];
    const float* cosb  = (const float*)d_in[1];
    const float* sinb  = (const float*)d_in[2];
    const float* wq    = (const float*)d_in[3];
    const float* wkv_a = (const float*)d_in[4];
    const float* knw   = (const float*)d_in[5];
    const float* wkv_b = (const float*)d_in[6];
    const float* wo    = (const float*)d_in[7];
    float* out = (float*)d_out;

    cudaFuncSetAttribute(tgemm<3>, cudaFuncAttributeMaxDynamicSharedMemorySize,
                         DSMEM_BYTES);
    cudaFuncSetAttribute(tgemm<1>, cudaFuncAttributeMaxDynamicSharedMemorySize,
                         DSMEM_BYTES);

    __nv_bfloat16 *xhi,*xlo,*wqkvhi,*wqkvlo,*wohi,*wolo,*wkvbhi,*wkvblo;
    __nv_bfloat16 *qchi,*qclo,*keffhi,*kefflo,*kfullhi;
    __nv_bfloat16 *vThi,*vTlo,*attnhi,*attnlo,*o2hi,*o2lo;
    float *o2p;
    cudaGetSymbolAddress((void**)&xhi, d_xhi);       cudaGetSymbolAddress((void**)&xlo, d_xlo);
    cudaGetSymbolAddress((void**)&wqkvhi, d_wqkvhi); cudaGetSymbolAddress((void**)&wqkvlo, d_wqkvlo);
    cudaGetSymbolAddress((void**)&wohi, d_wohi);     cudaGetSymbolAddress((void**)&wolo, d_wolo);
    cudaGetSymbolAddress((void**)&wkvbhi, d_wkvbhi); cudaGetSymbolAddress((void**)&wkvblo, d_wkvblo);
    cudaGetSymbolAddress((void**)&qchi, d_qchi);     cudaGetSymbolAddress((void**)&qclo, d_qclo);
    cudaGetSymbolAddress((void**)&keffhi, d_keffhi); cudaGetSymbolAddress((void**)&kefflo, d_kefflo);
    cudaGetSymbolAddress((void**)&kfullhi, d_kfullhi);
    cudaGetSymbolAddress((void**)&vThi, d_vThi);     cudaGetSymbolAddress((void**)&vTlo, d_vTlo);
    cudaGetSymbolAddress((void**)&attnhi, d_attnhi); cudaGetSymbolAddress((void**)&attnlo, d_attnlo);
    cudaGetSymbolAddress((void**)&o2p, d_o2p);
    cudaGetSymbolAddress((void**)&o2hi, d_o2hi);     cudaGetSymbolAddress((void**)&o2lo, d_o2lo);

    // -------- operand splits --------
    {
        long n4;
        n4 = (long)S_ * DIM_ / 4;
        split_kernel<<<(n4 + 255) / 256, 256>>>(
            (const float4*)x, (__nv_bfloat162*)xhi, (__nv_bfloat162*)xlo, n4);
        n4 = (long)NQKV_ * DIM_ / 4;
        split_concat_wqkv<<<(n4 + 255) / 256, 256>>>(
            (const float4*)wq, (const float4*)wkv_a,
            (__nv_bfloat162*)wqkvhi, (__nv_bfloat162*)wqkvlo);
        n4 = (long)DIM_ * DIM_ / 4;
        split_kernel<<<(n4 + 255) / 256, 256>>>(
            (const float4*)wo, (__nv_bfloat162*)wohi, (__nv_bfloat162*)wolo, n4);
        n4 = (long)H_ * 256 * LORA_ / 4;
        split_kernel<<<(n4 + 255) / 256, 256>>>(
            (const float4*)wkv_b, (__nv_bfloat162*)wkvbhi, (__nv_bfloat162*)wkvblo, n4);
    }

    // 1. [q | kv] = x @ [wq | wkv_a]^T  (2048 x 3712), hi/lo (3-term)
    tgemm<3><<<dim3(NQKV_ / 128, 16, 1), 256, DSMEM_BYTES>>>(
        xhi, xlo, 0, DIM_, wqkvhi, wqkvlo, 0, DIM_,
        nullptr, qchi, qclo, 0, NQKV_, DIM_, 1.f, 0, 0, 0);

    // 2. prep: rmsnorm + rope (q in place, k_pe into kfull hi, keff out)
    prep_kernel<<<S_, 256>>>(qchi, qclo, cosb, sinb, knw,
                             keffhi, kefflo, kfullhi);

    // 3. k_nope[h] = keff @ w_uk[h]^T -> kfull[h] cols 0..127 (1-term, hi out)
    tgemm<1><<<dim3(1, 16, H_), 256, DSMEM_BYTES>>>(
        keffhi, nullptr, 0, LORA_,
        wkvbhi, nullptr, (long)256 * LORA_, LORA_,
        nullptr, kfullhi, nullptr, (long)S_ * KQK_, KQK_, LORA_, 1.f, 0, 0, 0);

    // 4. vT[h] = w_uv[h] @ keff^T  (M=128 d, N=2048 t, K=512) (3-term)
    tgemm<3><<<dim3(16, 1, H_), 256, DSMEM_BYTES>>>(
        wkvbhi + (long)NOPE_ * LORA_, wkvblo + (long)NOPE_ * LORA_,
        (long)256 * LORA_, LORA_,
        keffhi, kefflo, 0, LORA_,
        nullptr, vThi, vTlo, (long)VD_ * S_, S_, LORA_, 1.f, 0, 0, 0);

    // 5. scores[h] = SCALE * q[h](K=192) @ kfull[h]^T (1-term, hi out, causal skip)
    tgemm<1><<<dim3(16, 16, H_), 256, DSMEM_BYTES>>>(
        qchi, nullptr, (long)QKH_, NQKV_,
        kfullhi, nullptr, (long)S_ * KQK_, KQK_,
        nullptr, attnhi, nullptr, (long)S_ * S_, S_, KQK_, SCALE_, 1, 0, 0);

    // 6. softmax: scores hi -> attn hi/lo
    softmax_kernel<<<dim3(S_, H_), 256>>>(attnhi, attnlo);

    // 7. o2 partials[split] = attn[h] @ vT[h]^T  (3-term, diag K, 2-way split-K)
    //    split 0: k in [0,1024); split 1: k in [1024, Klim)   -> fp32 partials
    //    output col block = h*128 within each 2048-wide partial buffer
    tgemm<3><<<dim3(2, 16, H_), 256, DSMEM_BYTES>>>(
        attnhi, attnlo, (long)S_ * S_, S_,
        vThi, vTlo, (long)VD_ * S_, S_,
        o2p, nullptr, nullptr, (long)VD_, DIM_, S_, 1.f, 2,
        1024, (long)S_ * DIM_);

    // 7b. o2 = o2p[0] + o2p[1] (rows >= 1024), split to hi/lo
    {
        long n4 = (long)S_ * DIM_ / 4;
        o2add_kernel<<<(n4 + 255) / 256, 256>>>(
            (const float4*)o2p, (const float4*)(o2p + (long)S_ * DIM_),
            (__nv_bfloat162*)o2hi, (__nv_bfloat162*)o2lo);
    }

    // 8. out = o2 @ wo^T  (3-term)
    tgemm<3><<<dim3(16, 16, 1), 256, DSMEM_BYTES>>>(
        o2hi, o2lo, 0, DIM_, wohi, wolo, 0, DIM_,
        out, nullptr, nullptr, 0, DIM_, DIM_, 1.f, 0, 0, 0);
}

// round 12
// speedup vs baseline: 2.0209x; 1.1695x over previous
#include <cuda_runtime.h>
#include <cuda_bf16.h>
#include <cstdint>

// ---------------------------------------------------------------------------
// Problem constants
// ---------------------------------------------------------------------------
#define S_ 2048
#define DIM_ 2048
#define H_ 16
#define NOPE_ 128
#define ROPE_ 64
#define VD_ 128
#define LORA_ 512
#define QKH_ 192            // NOPE + ROPE
#define KVW_ 576            // LORA + ROPE
#define KVP_ 640            // kv padded to multiple of 128
#define NQKV_ 3712          // 3072 (q) + 640 (kv padded)
#define KQK_ 192            // per-head qk dim after reassociation
#define SCALE_ 0.07216878364870323f  // 192^-0.5

// ---------------------------------------------------------------------------
// Scratch
// ---------------------------------------------------------------------------
__device__ __nv_bfloat16 d_xhi[(long)S_ * DIM_],      d_xlo[(long)S_ * DIM_];
__device__ __nv_bfloat16 d_wqhi[(long)3072 * DIM_];                                // hi only
__device__ __nv_bfloat16 d_wkvahi[(long)KVP_ * DIM_], d_wkvalo[(long)KVP_ * DIM_];
__device__ __nv_bfloat16 d_wohi[(long)DIM_ * DIM_],   d_wolo[(long)DIM_ * DIM_];
__device__ __nv_bfloat16 d_wkvbhi[(long)H_ * 256 * LORA_], d_wkvblo[(long)H_ * 256 * LORA_];
__device__ __nv_bfloat16 d_qchi[(long)S_ * NQKV_],    d_qclo[(long)S_ * NQKV_];   // lo used for kv cols only
__device__ __nv_bfloat16 d_keffhi[(long)S_ * LORA_],  d_kefflo[(long)S_ * LORA_]; // normed kv_c
__device__ __nv_bfloat16 d_kfullhi[(long)H_ * S_ * KQK_];                         // [k_nope | k_pe], hi only
__device__ __nv_bfloat16 d_vThi[(long)H_ * VD_ * S_], d_vTlo[(long)H_ * VD_ * S_];
__device__ __nv_bfloat16 d_attnhi[(long)H_ * S_ * S_],d_attnlo[(long)H_ * S_ * S_];
__device__ float         d_o2p[2][(long)S_ * DIM_];   // split-K fp32 partials
__device__ __nv_bfloat16 d_o2hi[(long)S_ * DIM_],     d_o2lo[(long)S_ * DIM_];

// ---------------------------------------------------------------------------
// Helpers
// ---------------------------------------------------------------------------
__device__ __forceinline__ uint32_t smem_u32(const void* p) {
    uint32_t a;
    asm("{ .reg .u64 t; cvta.to.shared.u64 t, %1; cvt.u32.u64 %0, t; }"
        : "=r"(a) : "l"(p));
    return a;
}

__device__ __forceinline__ void ldsm_x4(uint32_t* r, uint32_t addr) {
    asm volatile("ldmatrix.sync.aligned.m8n8.x4.shared.b16 {%0,%1,%2,%3}, [%4];"
                 : "=r"(r[0]), "=r"(r[1]), "=r"(r[2]), "=r"(r[3]) : "r"(addr));
}
__device__ __forceinline__ void ldsm_x2(uint32_t* r, uint32_t addr) {
    asm volatile("ldmatrix.sync.aligned.m8n8.x2.shared.b16 {%0,%1}, [%2];"
                 : "=r"(r[0]), "=r"(r[1]) : "r"(addr));
}
__device__ __forceinline__ void mma16816(float* c, const uint32_t* a, const uint32_t* b) {
    asm volatile(
        "mma.sync.aligned.m16n8k16.row.col.f32.bf16.bf16.f32 "
        "{%0,%1,%2,%3}, {%4,%5,%6,%7}, {%8,%9}, {%0,%1,%2,%3};"
        : "+f"(c[0]), "+f"(c[1]), "+f"(c[2]), "+f"(c[3])
        : "r"(a[0]), "r"(a[1]), "r"(a[2]), "r"(a[3]), "r"(b[0]), "r"(b[1]));
}

__device__ __forceinline__ void split2(float v, __nv_bfloat16& h, __nv_bfloat16& l) {
    h = __float2bfloat16(v);
    l = __float2bfloat16(v - __bfloat162float(h));
}
__device__ __forceinline__ float rec2(__nv_bfloat16 h, __nv_bfloat16 l) {
    return __bfloat162float(h) + __bfloat162float(l);
}

// ---------------------------------------------------------------------------
// bf16 split-precision GEMM via mma.sync:
//   C(z) = alpha * A(z)(M,K) @ B(z)(N,K)^T
//   TERMS==3: C ~= Ahi.Bhi + Ahi.Blo + Alo.Bhi ; TERMS==1: C ~= Ahi.Bhi
// CTA tile 128x128, K chunk 32, cp.async double buffer, 2 CTAs/SM.
// causal: 1 = skip tiles with bx > by; 2 = Klim = min(K, row0+128)
// ksplit > 0: split-K mode (N==128): bx = K-split index, Cf += bx*sSplit.
// ---------------------------------------------------------------------------
#define TILE_B 10240            // 128 * 80
#define STAGE_B 40960           // 4 tiles
#define DSMEM_BYTES 81920       // 2 stages

__device__ __forceinline__ void load_tile32(uint32_t dst,
                                            const __nv_bfloat16* __restrict__ src,
                                            int rbase, int ld, int k0, int tid)
{
#pragma unroll
    for (int t = 0; t < 2; t++) {
        int o = tid + t * 256;          // 0..511 : 128 rows x 4 x 16B
        int row = o >> 2, c = o & 3;
        const void* g = (const void*)(src + (long)(rbase + row) * ld + k0 + c * 8);
        asm volatile("cp.async.cg.shared.global [%0], [%1], 16;"
                     :: "r"(dst + row * 80 + c * 16), "l"(g));
    }
}

template <int TERMS>
__global__ void __launch_bounds__(256, 2)
tgemm(const __nv_bfloat16* __restrict__ Ahi, const __nv_bfloat16* __restrict__ Alo,
      long sA, int lda,
      const __nv_bfloat16* __restrict__ Bhi, const __nv_bfloat16* __restrict__ Blo,
      long sB, int ldb,
      float* Cf, __nv_bfloat16* Chi, __nv_bfloat16* Clo,
      long sC, int ldc,
      int K, float alpha, int causal,
      int ksplit, long sSplit)
{
    const int bx = blockIdx.x, by = blockIdx.y, z = blockIdx.z;
    if (causal == 1 && bx > by) return;
    const int row0 = by * 128;
    int col0 = bx * 128;
    int Klim = (causal == 2) ? min(K, row0 + 128) : K;
    int kstart = 0, kend = Klim;
    if (ksplit > 0) {
        col0 = 0;
        kstart = bx * ksplit;
        kend = min(Klim, kstart + ksplit);
        if (kstart >= kend) return;
        if (Cf) Cf += (long)bx * sSplit;
    }
    const int c0 = kstart >> 5, c1 = kend >> 5;

    Ahi += (long)z * sA;
    Bhi += (long)z * sB;
    if (TERMS == 3) { Alo += (long)z * sA; Blo += (long)z * sB; }
    if (Cf)  Cf  += (long)z * sC;
    if (Chi) Chi += (long)z * sC;
    if (Clo) Clo += (long)z * sC;

    extern __shared__ char dsm[];
    const uint32_t s0 = smem_u32(dsm);

    const int tid = threadIdx.x;
    const int lane = tid & 31;
    const int wid = tid >> 5;
    const int wm = wid & 1;          // 0..1  (M)
    const int wn = wid >> 1;         // 0..3  (N)

    float acc[4][4][4];
#pragma unroll
    for (int mt = 0; mt < 4; mt++)
#pragma unroll
        for (int nt = 0; nt < 4; nt++)
#pragma unroll
            for (int e = 0; e < 4; e++) acc[mt][nt][e] = 0.f;

    // prologue: fill stage (c0 & 1)
    {
        uint32_t sb = s0 + (c0 & 1) * STAGE_B;
        int k0 = c0 << 5;
        load_tile32(sb,              Ahi, row0, lda, k0, tid);
        load_tile32(sb + 2 * TILE_B, Bhi, col0, ldb, k0, tid);
        if (TERMS == 3) {
            load_tile32(sb + TILE_B,     Alo, row0, lda, k0, tid);
            load_tile32(sb + 3 * TILE_B, Blo, col0, ldb, k0, tid);
        }
        asm volatile("cp.async.commit_group;" ::: "memory");
    }

    const uint32_t a_off = (wm * 64 + (lane & 15)) * 80 + ((lane >> 4) << 4);
    const uint32_t b_off = (wn * 32 + (lane & 7)) * 80 + (((lane >> 3) & 1) << 4);

    for (int i = c0; i < c1; i++) {
        if (i + 1 < c1) {
            uint32_t sb = s0 + ((i + 1) & 1) * STAGE_B;
            int k0 = (i + 1) << 5;
            load_tile32(sb,              Ahi, row0, lda, k0, tid);
            load_tile32(sb + 2 * TILE_B, Bhi, col0, ldb, k0, tid);
            if (TERMS == 3) {
                load_tile32(sb + TILE_B,     Alo, row0, lda, k0, tid);
                load_tile32(sb + 3 * TILE_B, Blo, col0, ldb, k0, tid);
            }
            asm volatile("cp.async.commit_group;" ::: "memory");
            asm volatile("cp.async.wait_group 1;" ::: "memory");
        } else {
            asm volatile("cp.async.wait_group 0;" ::: "memory");
        }
        __syncthreads();

        const uint32_t sb = s0 + (i & 1) * STAGE_B;
#pragma unroll
        for (int ks = 0; ks < 2; ks++) {
            const uint32_t kb = ks * 32;
            uint32_t bh[4][2], bl[4][2];
#pragma unroll
            for (int nt = 0; nt < 4; nt++) {
                ldsm_x2(bh[nt], sb + 2 * TILE_B + b_off + nt * (8 * 80) + kb);
                if (TERMS == 3)
                    ldsm_x2(bl[nt], sb + 3 * TILE_B + b_off + nt * (8 * 80) + kb);
            }
#pragma unroll
            for (int mt = 0; mt < 4; mt++) {
                uint32_t ah[4], al[4];
                ldsm_x4(ah, sb + a_off + mt * (16 * 80) + kb);
                if (TERMS == 3)
                    ldsm_x4(al, sb + TILE_B + a_off + mt * (16 * 80) + kb);
#pragma unroll
                for (int nt = 0; nt < 4; nt++) {
                    mma16816(acc[mt][nt], ah, bh[nt]);
                    if (TERMS == 3) {
                        mma16816(acc[mt][nt], ah, bl[nt]);
                        mma16816(acc[mt][nt], al, bh[nt]);
                    }
                }
            }
        }
        __syncthreads();
    }

    // ---------------- epilogue: stage through smem ----------------
    float* stage = (float*)dsm;   // pitch 132 f32: 128*132*4 = 67584 <= 81920
#pragma unroll
    for (int mt = 0; mt < 4; mt++) {
        int r = wm * 64 + mt * 16 + (lane >> 2);
#pragma unroll
        for (int nt = 0; nt < 4; nt++) {
            int c = wn * 32 + nt * 8 + (lane & 3) * 2;
            stage[r * 132 + c]           = acc[mt][nt][0] * alpha;
            stage[r * 132 + c + 1]       = acc[mt][nt][1] * alpha;
            stage[(r + 8) * 132 + c]     = acc[mt][nt][2] * alpha;
            stage[(r + 8) * 132 + c + 1] = acc[mt][nt][3] * alpha;
        }
    }
    __syncthreads();

#pragma unroll
    for (int it = 0; it < 16; it++) {
        int g = tid + it * 256;
        int m = g >> 5, cg = (g & 31) * 4;
        float v0 = stage[m * 132 + cg + 0];
        float v1 = stage[m * 132 + cg + 1];
        float v2 = stage[m * 132 + cg + 2];
        float v3 = stage[m * 132 + cg + 3];
        long off = (long)(row0 + m) * ldc + col0 + cg;
        if (Cf) {
            float4 v = make_float4(v0, v1, v2, v3);
            *(float4*)(Cf + off) = v;
        }
        if (Chi) {
            __nv_bfloat16 h0, h1, h2, h3, l0, l1, l2, l3;
            split2(v0, h0, l0); split2(v1, h1, l1);
            split2(v2, h2, l2); split2(v3, h3, l3);
            *(__nv_bfloat162*)(Chi + off)     = __nv_bfloat162(h0, h1);
            *(__nv_bfloat162*)(Chi + off + 2) = __nv_bfloat162(h2, h3);
            if (Clo) {
                *(__nv_bfloat162*)(Clo + off)     = __nv_bfloat162(l0, l1);
                *(__nv_bfloat162*)(Clo + off + 2) = __nv_bfloat162(l2, l3);
            }
        }
    }
}

// ---------------------------------------------------------------------------
// Pointwise / prep kernels
// ---------------------------------------------------------------------------
__global__ void split_kernel(const float4* __restrict__ in,
                             __nv_bfloat162* __restrict__ hi,
                             __nv_bfloat162* __restrict__ lo, long n4)
{
    long i = (long)blockIdx.x * blockDim.x + threadIdx.x;
    if (i < n4) {
        float4 v = in[i];
        __nv_bfloat16 h0, h1, h2, h3, l0, l1, l2, l3;
        split2(v.x, h0, l0); split2(v.y, h1, l1);
        split2(v.z, h2, l2); split2(v.w, h3, l3);
        hi[2 * i]     = __nv_bfloat162(h0, h1);
        hi[2 * i + 1] = __nv_bfloat162(h2, h3);
        lo[2 * i]     = __nv_bfloat162(l0, l1);
        lo[2 * i + 1] = __nv_bfloat162(l2, l3);
    }
}

// hi-only split (for wq: only the bf16 hi part is ever consumed)
__global__ void split_hi_kernel(const float4* __restrict__ in,
                                __nv_bfloat162* __restrict__ hi, long n4)
{
    long i = (long)blockIdx.x * blockDim.x + threadIdx.x;
    if (i < n4) {
        float4 v = in[i];
        hi[2 * i]     = __nv_bfloat162(__float2bfloat16(v.x), __float2bfloat16(v.y));
        hi[2 * i + 1] = __nv_bfloat162(__float2bfloat16(v.z), __float2bfloat16(v.w));
    }
}

// pad wkv_a (576 x 2048) -> (640 x 2048) with zero rows, split hi/lo
__global__ void padsplit_wkva(const float4* __restrict__ in,
                              __nv_bfloat162* __restrict__ hi,
                              __nv_bfloat162* __restrict__ lo)
{
    long i = (long)blockIdx.x * blockDim.x + threadIdx.x;  // float4 index
    long n4 = (long)KVP_ * DIM_ / 4;
    if (i < n4) {
        long r = i / (DIM_ / 4);
        float4 v = (r < KVW_) ? in[i] : make_float4(0.f, 0.f, 0.f, 0.f);
        __nv_bfloat16 h0, h1, h2, h3, l0, l1, l2, l3;
        split2(v.x, h0, l0); split2(v.y, h1, l1);
        split2(v.z, h2, l2); split2(v.w, h3, l3);
        hi[2 * i]     = __nv_bfloat162(h0, h1);
        hi[2 * i + 1] = __nv_bfloat162(h2, h3);
        lo[2 * i]     = __nv_bfloat162(l0, l1);
        lo[2 * i + 1] = __nv_bfloat162(l2, l3);
    }
}

// o2 = o2a + (row >= 1024 ? o2b : 0), split to hi/lo. 4 floats/thread.
__global__ void o2add_kernel(const float4* __restrict__ a,
                             const float4* __restrict__ b,
                             __nv_bfloat162* __restrict__ hi,
                             __nv_bfloat162* __restrict__ lo)
{
    long i = (long)blockIdx.x * blockDim.x + threadIdx.x;  // float4 index
    long n4 = (long)S_ * DIM_ / 4;
    if (i < n4) {
        long row = i / (DIM_ / 4);
        float4 v = a[i];
        if (row >= 1024) {
            float4 w = b[i];
            v.x += w.x; v.y += w.y; v.z += w.z; v.w += w.w;
        }
        __nv_bfloat16 h0, h1, h2, h3, l0, l1, l2, l3;
        split2(v.x, h0, l0); split2(v.y, h1, l1);
        split2(v.z, h2, l2); split2(v.w, h3, l3);
        hi[2 * i]     = __nv_bfloat162(h0, h1);
        hi[2 * i + 1] = __nv_bfloat162(h2, h3);
        lo[2 * i]     = __nv_bfloat162(l0, l1);
        lo[2 * i + 1] = __nv_bfloat162(l2, l3);
    }
}

// rmsnorm(kv_c) -> keff hi/lo ; rope(k_pe) -> kfull cols 128..191 (hi only);
// rope(q_pe) in place in qchi (hi only; q path is 1-term downstream).
__global__ void prep_kernel(__nv_bfloat16* __restrict__ qchi,
                            __nv_bfloat16* __restrict__ qclo,
                            const float* __restrict__ cosb,
                            const float* __restrict__ sinb,
                            const float* __restrict__ knw,
                            __nv_bfloat16* __restrict__ keffhi,
                            __nv_bfloat16* __restrict__ kefflo,
                            __nv_bfloat16* __restrict__ kfullhi)
{
    const int s = blockIdx.x;
    const int tid = threadIdx.x;
    __nv_bfloat16* kvhi = qchi + (long)s * NQKV_ + 3072;
    __nv_bfloat16* kvlo = qclo + (long)s * NQKV_ + 3072;
    __shared__ float red[256];

    float ss = 0.f;
    for (int c = tid; c < LORA_; c += 256) {
        float v = rec2(kvhi[c], kvlo[c]);
        ss += v * v;
    }
    red[tid] = ss;
    __syncthreads();
    for (int w = 128; w > 0; w >>= 1) {
        if (tid < w) red[tid] += red[tid + w];
        __syncthreads();
    }
    float r = rsqrtf(red[0] / (float)LORA_ + 1e-6f);
    for (int c = tid; c < LORA_; c += 256) {
        float v = rec2(kvhi[c], kvlo[c]);
        __nv_bfloat16 h, l;
        split2(v * r * knw[c], h, l);
        keffhi[(long)s * LORA_ + c] = h;
        kefflo[(long)s * LORA_ + c] = l;
    }

    const float* cs = cosb + s * (ROPE_ / 2);
    const float* sn = sinb + s * (ROPE_ / 2);

    // rope k_pe -> kfull[h][s][128+...] for all 16 heads (hi only)
    for (int idx = tid; idx < H_ * 32; idx += 256) {
        int h = idx >> 5, i = idx & 31;
        float x0 = rec2(kvhi[LORA_ + 2 * i], kvlo[LORA_ + 2 * i]);
        float x1 = rec2(kvhi[LORA_ + 2 * i + 1], kvlo[LORA_ + 2 * i + 1]);
        float y0 = x0 * cs[i] - x1 * sn[i];
        float y1 = x0 * sn[i] + x1 * cs[i];
        long base = ((long)h * S_ + s) * KQK_ + NOPE_;
        kfullhi[base + 2 * i]     = __float2bfloat16(y0);
        kfullhi[base + 2 * i + 1] = __float2bfloat16(y1);
    }

    // rope q_pe in place, hi only (q is consumed 1-term)
    for (int idx = tid; idx < H_ * 32; idx += 256) {
        int h = idx >> 5, i = idx & 31;
        long base = (long)s * NQKV_ + h * QKH_ + NOPE_;
        float x0 = __bfloat162float(qchi[base + 2 * i]);
        float x1 = __bfloat162float(qchi[base + 2 * i + 1]);
        float y0 = x0 * cs[i] - x1 * sn[i];
        float y1 = x0 * sn[i] + x1 * cs[i];
        qchi[base + 2 * i]     = __float2bfloat16(y0);
        qchi[base + 2 * i + 1] = __float2bfloat16(y1);
    }
}

// causal softmax: read scores (bf16 hi only, in attnhi), write attn hi/lo.
__global__ void softmax_kernel(__nv_bfloat16* __restrict__ attnhi,
                               __nv_bfloat16* __restrict__ attnlo)
{
    const int s = blockIdx.x, h = blockIdx.y;
    __nv_bfloat16* ohi = attnhi + ((long)h * S_ + s) * S_;
    __nv_bfloat16* olo = attnlo + ((long)h * S_ + s) * S_;
    const int n = s + 1;
    const int nz = ((s >> 7) + 1) << 7;   // round up to 128
    const int tid = threadIdx.x;
    const int lane = tid & 31, wid = tid >> 5;
    const int c0 = tid * 8;
    __shared__ float wred[8];

    float vals[8];
    float m = -1e30f;
    if (c0 < nz) {
        uint4 hv = *(const uint4*)(ohi + c0);
        const __nv_bfloat162* hp = (const __nv_bfloat162*)&hv;
#pragma unroll
        for (int j = 0; j < 4; j++) {
            float2 hf = __bfloat1622float2(hp[j]);
            vals[2 * j]     = hf.x;
            vals[2 * j + 1] = hf.y;
        }
#pragma unroll
        for (int j = 0; j < 8; j++)
            if (c0 + j < n) m = fmaxf(m, vals[j]);
    }
#pragma unroll
    for (int o = 16; o > 0; o >>= 1)
        m = fmaxf(m, __shfl_xor_sync(0xffffffffu, m, o));
    if (lane == 0) wred[wid] = m;
    __syncthreads();
    m = -1e30f;
#pragma unroll
    for (int w = 0; w < 8; w++) m = fmaxf(m, wred[w]);
    __syncthreads();

    float sum = 0.f;
    if (c0 < nz) {
#pragma unroll
        for (int j = 0; j < 8; j++) {
            float e = (c0 + j < n) ? __expf(vals[j] - m) : 0.f;
            vals[j] = e;
            sum += e;
        }
    }
#pragma unroll
    for (int o = 16; o > 0; o >>= 1)
        sum += __shfl_xor_sync(0xffffffffu, sum, o);
    if (lane == 0) wred[wid] = sum;
    __syncthreads();
    sum = 0.f;
#pragma unroll
    for (int w = 0; w < 8; w++) sum += wred[w];
    float inv = 1.0f / sum;

    if (c0 < nz) {
        __nv_bfloat162 hv[4], lv[4];
#pragma unroll
        for (int j = 0; j < 4; j++) {
            __nv_bfloat16 h0, h1, l0, l1;
            split2(vals[2 * j] * inv, h0, l0);
            split2(vals[2 * j + 1] * inv, h1, l1);
            hv[j] = __nv_bfloat162(h0, h1);
            lv[j] = __nv_bfloat162(l0, l1);
        }
        *(uint4*)(ohi + c0) = *(uint4*)hv;
        *(uint4*)(olo + c0) = *(uint4*)lv;
    }
}

// ---------------------------------------------------------------------------
// Launch
// ---------------------------------------------------------------------------
extern "C" void kernel_launch(void* const* d_in, const int* in_sizes, int n_in,
                              void* d_out, int out_size)
{
    const float* x     = (const float*)d_in[0];
    const float* cosb  = (const float*)d_in[1];
    const float* sinb  = (const float*)d_in[2];
    const float* wq    = (const float*)d_in[3];
    const float* wkv_a = (const float*)d_in[4];
    const float* knw   = (const float*)d_in[5];
    const float* wkv_b = (const float*)d_in[6];
    const float* wo    = (const float*)d_in[7];
    float* out = (float*)d_out;

    cudaFuncSetAttribute(tgemm<3>, cudaFuncAttributeMaxDynamicSharedMemorySize,
                         DSMEM_BYTES);
    cudaFuncSetAttribute(tgemm<1>, cudaFuncAttributeMaxDynamicSharedMemorySize,
                         DSMEM_BYTES);

    __nv_bfloat16 *xhi,*xlo,*wqhi,*wkvahi,*wkvalo,*wohi,*wolo,*wkvbhi,*wkvblo;
    __nv_bfloat16 *qchi,*qclo,*keffhi,*kefflo,*kfullhi;
    __nv_bfloat16 *vThi,*vTlo,*attnhi,*attnlo,*o2hi,*o2lo;
    float *o2p;
    cudaGetSymbolAddress((void**)&xhi, d_xhi);       cudaGetSymbolAddress((void**)&xlo, d_xlo);
    cudaGetSymbolAddress((void**)&wqhi, d_wqhi);
    cudaGetSymbolAddress((void**)&wkvahi, d_wkvahi); cudaGetSymbolAddress((void**)&wkvalo, d_wkvalo);
    cudaGetSymbolAddress((void**)&wohi, d_wohi);     cudaGetSymbolAddress((void**)&wolo, d_wolo);
    cudaGetSymbolAddress((void**)&wkvbhi, d_wkvbhi); cudaGetSymbolAddress((void**)&wkvblo, d_wkvblo);
    cudaGetSymbolAddress((void**)&qchi, d_qchi);     cudaGetSymbolAddress((void**)&qclo, d_qclo);
    cudaGetSymbolAddress((void**)&keffhi, d_keffhi); cudaGetSymbolAddress((void**)&kefflo, d_kefflo);
    cudaGetSymbolAddress((void**)&kfullhi, d_kfullhi);
    cudaGetSymbolAddress((void**)&vThi, d_vThi);     cudaGetSymbolAddress((void**)&vTlo, d_vTlo);
    cudaGetSymbolAddress((void**)&attnhi, d_attnhi); cudaGetSymbolAddress((void**)&attnlo, d_attnlo);
    cudaGetSymbolAddress((void**)&o2p, d_o2p);
    cudaGetSymbolAddress((void**)&o2hi, d_o2hi);     cudaGetSymbolAddress((void**)&o2lo, d_o2lo);

    // -------- operand splits --------
    {
        long n4;
        n4 = (long)S_ * DIM_ / 4;
        split_kernel<<<(n4 + 255) / 256, 256>>>(
            (const float4*)x, (__nv_bfloat162*)xhi, (__nv_bfloat162*)xlo, n4);
        n4 = (long)3072 * DIM_ / 4;
        split_hi_kernel<<<(n4 + 255) / 256, 256>>>(
            (const float4*)wq, (__nv_bfloat162*)wqhi, n4);
        n4 = (long)KVP_ * DIM_ / 4;
        padsplit_wkva<<<(n4 + 255) / 256, 256>>>(
            (const float4*)wkv_a, (__nv_bfloat162*)wkvahi, (__nv_bfloat162*)wkvalo);
        n4 = (long)DIM_ * DIM_ / 4;
        split_kernel<<<(n4 + 255) / 256, 256>>>(
            (const float4*)wo, (__nv_bfloat162*)wohi, (__nv_bfloat162*)wolo, n4);
        n4 = (long)H_ * 256 * LORA_ / 4;
        split_kernel<<<(n4 + 255) / 256, 256>>>(
            (const float4*)wkv_b, (__nv_bfloat162*)wkvbhi, (__nv_bfloat162*)wkvblo, n4);
    }

    // 1a. q = x @ wq^T  (2048 x 3072), 1-term, hi-only output into qc cols 0..3071
    tgemm<1><<<dim3(3072 / 128, 16, 1), 256, DSMEM_BYTES>>>(
        xhi, nullptr, 0, DIM_, wqhi, nullptr, 0, DIM_,
        nullptr, qchi, nullptr, 0, NQKV_, DIM_, 1.f, 0, 0, 0);

    // 1b. kv = x @ wkv_a_pad^T  (2048 x 640), 3-term, hi/lo into qc cols 3072..3711
    tgemm<3><<<dim3(KVP_ / 128, 16, 1), 256, DSMEM_BYTES>>>(
        xhi, xlo, 0, DIM_, wkvahi, wkvalo, 0, DIM_,
        nullptr, qchi + 3072, qclo + 3072, 0, NQKV_, DIM_, 1.f, 0, 0, 0);

    // 2. prep: rmsnorm + rope (q hi in place, k_pe into kfull hi, keff out)
    prep_kernel<<<S_, 256>>>(qchi, qclo, cosb, sinb, knw,
                             keffhi, kefflo, kfullhi);

    // 3. k_nope[h] = keff @ w_uk[h]^T -> kfull[h] cols 0..127 (1-term, hi out)
    tgemm<1><<<dim3(1, 16, H_), 256, DSMEM_BYTES>>>(
        keffhi, nullptr, 0, LORA_,
        wkvbhi, nullptr, (long)256 * LORA_, LORA_,
        nullptr, kfullhi, nullptr, (long)S_ * KQK_, KQK_, LORA_, 1.f, 0, 0, 0);

    // 4. vT[h] = w_uv[h] @ keff^T  (M=128 d, N=2048 t, K=512) (3-term)
    tgemm<3><<<dim3(16, 1, H_), 256, DSMEM_BYTES>>>(
        wkvbhi + (long)NOPE_ * LORA_, wkvblo + (long)NOPE_ * LORA_,
        (long)256 * LORA_, LORA_,
        keffhi, kefflo, 0, LORA_,
        nullptr, vThi, vTlo, (long)VD_ * S_, S_, LORA_, 1.f, 0, 0, 0);

    // 5. scores[h] = SCALE * q[h](K=192) @ kfull[h]^T (1-term, hi out, causal skip)
    tgemm<1><<<dim3(16, 16, H_), 256, DSMEM_BYTES>>>(
        qchi, nullptr, (long)QKH_, NQKV_,
        kfullhi, nullptr, (long)S_ * KQK_, KQK_,
        nullptr, attnhi, nullptr, (long)S_ * S_, S_, KQK_, SCALE_, 1, 0, 0);

    // 6. softmax: scores hi -> attn hi/lo
    softmax_kernel<<<dim3(S_, H_), 256>>>(attnhi, attnlo);

    // 7. o2 partials = attn[h] @ vT[h]^T  (3-term, diag K, 2-way split-K, fp32)
    tgemm<3><<<dim3(2, 16, H_), 256, DSMEM_BYTES>>>(
        attnhi, attnlo, (long)S_ * S_, S_,
        vThi, vTlo, (long)VD_ * S_, S_,
        o2p, nullptr, nullptr, (long)VD_, DIM_, S_, 1.f, 2,
        1024, (long)S_ * DIM_);

    // 7b. o2 = o2p[0] + o2p[1] (rows >= 1024), split to hi/lo
    {
        long n4 = (long)S_ * DIM_ / 4;
        o2add_kernel<<<(n4 + 255) / 256, 256>>>(
            (const float4*)o2p, (const float4*)(o2p + (long)S_ * DIM_),
            (__nv_bfloat162*)o2hi, (__nv_bfloat162*)o2lo);
    }

    // 8. out = o2 @ wo^T  (3-term)
    tgemm<3><<<dim3(16, 16, 1), 256, DSMEM_BYTES>>>(
        o2hi, o2lo, 0, DIM_, wohi, wolo, 0, DIM_,
        out, nullptr, nullptr, 0, DIM_, DIM_, 1.f, 0, 0, 0);
}